// round 1
// baseline (speedup 1.0000x reference)
#include <cuda_runtime.h>
#include <math.h>

// ============================================================
// Scratch (device globals -- no allocation allowed)
// ============================================================
__device__ float g_h1 [33554432];  // [16,128,128,128]: enc h1, later dec t1 output
__device__ float g_a  [16777216];  // [16,256,64,64]
__device__ float g_b  [16777216];  // [16,256,64,64]
__device__ float g_mid[ 2097152];  // [16,32,64,64]
__device__ float g_part[256 * 4];  // per-block VQ loss partials
__device__ int   g_cnt [4 * 512];  // VQ code counts

// Output layout (tuple order): x_recon | rq_loss | z_q | z_e | perps
#define OFF_XREC 0
#define OFF_LOSS 3145728
#define OFF_ZQ   3145729
#define OFF_ZE   7340033
#define OFF_PERP 11534337

// ============================================================
// Generic implicit-GEMM conv
// ============================================================
#define BM 64
#define BN 64
#define BK 16
#define KMAX 2304

struct ConvParams {
    const float* in; const float* w; const float* bias; const float* residual; float* out;
    int N, Cin, IH, IW, Cout, OH, OW;
    int KH, KW, KHW, Kdim;
    int stride, padH, padW;
    // weight index: co*wsCo + ci*wsCi + (kyOff+ky*kyStep)*wsKy + kxOff + kx*kxStep
    int wsCo, wsCi, wsKy, kyOff, kyStep, kxOff, kxStep;
    // output index: ((n*Cout+co)*OHfull + oyOff+oy*oyStep)*OWfull + oxOff+ox*oxStep
    int OHfull, OWfull, oyOff, oyStep, oxOff, oxStep;
    int inRelu, outRelu, addRes;
};

__global__ __launch_bounds__(256) void conv_gemm(ConvParams p)
{
    __shared__ float As[BK][BM + 4];
    __shared__ float Bs[BK][BN + 4];
    __shared__ int sWOff[KMAX];
    __shared__ int sBOff[KMAX];
    __shared__ int sKyx [KMAX];

    const int tid  = threadIdx.x;
    const int Kdim = p.Kdim;

    // Build k -> (weight offset, input offset, ky/kx) tables once per block
    for (int k = tid; k < Kdim; k += 256) {
        int ci = k / p.KHW; int r2 = k - ci * p.KHW;
        int ky = r2 / p.KW; int kx = r2 - ky * p.KW;
        sWOff[k] = ci * p.wsCi + (p.kyOff + ky * p.kyStep) * p.wsKy + p.kxOff + kx * p.kxStep;
        sBOff[k] = (ci * p.IH + ky) * p.IW + kx;
        sKyx[k]  = (ky << 16) | kx;
    }

    const int lane64 = tid & 63;
    const int kr     = tid >> 6;
    const int OHOW   = p.OH * p.OW;
    const int col    = blockIdx.y * BN + lane64;
    const int n      = col / OHOW; const int rem = col - n * OHOW;
    const int oy     = rem / p.OW; const int ox  = rem - oy * p.OW;
    const int iy0    = oy * p.stride - p.padH;
    const int ix0    = ox * p.stride - p.padW;
    const int inBase = (n * p.Cin * p.IH + iy0) * p.IW + ix0;

    const int  m      = blockIdx.x * BM + lane64;
    const bool mValid = (m < p.Cout);
    const float* wRow = p.w + (size_t)(mValid ? m : 0) * p.wsCo;

    float acc[4][4];
#pragma unroll
    for (int i = 0; i < 4; i++)
#pragma unroll
        for (int j = 0; j < 4; j++) acc[i][j] = 0.f;

    const int tx = tid & 15, ty = tid >> 4;

    __syncthreads();

    for (int k0 = 0; k0 < Kdim; k0 += BK) {
#pragma unroll
        for (int u = 0; u < 4; u++) {
            int k = k0 + kr * 4 + u;
            float a = 0.f, b = 0.f;
            if (k < Kdim) {
                if (mValid) a = __ldg(wRow + sWOff[k]);
                int kyx = sKyx[k];
                int iy = iy0 + (kyx >> 16);
                int ix = ix0 + (kyx & 0xffff);
                if ((unsigned)iy < (unsigned)p.IH && (unsigned)ix < (unsigned)p.IW) {
                    b = __ldg(p.in + inBase + sBOff[k]);
                    if (p.inRelu) b = fmaxf(b, 0.f);
                }
            }
            As[kr * 4 + u][lane64] = a;
            Bs[kr * 4 + u][lane64] = b;
        }
        __syncthreads();
#pragma unroll
        for (int kk = 0; kk < BK; kk++) {
            float4 av = *reinterpret_cast<const float4*>(&As[kk][ty * 4]);
            float4 bv = *reinterpret_cast<const float4*>(&Bs[kk][tx * 4]);
            float a4[4] = {av.x, av.y, av.z, av.w};
            float b4[4] = {bv.x, bv.y, bv.z, bv.w};
#pragma unroll
            for (int i = 0; i < 4; i++)
#pragma unroll
                for (int j = 0; j < 4; j++)
                    acc[i][j] = fmaf(a4[i], b4[j], acc[i][j]);
        }
        __syncthreads();
    }

    // Epilogue: bias (+residual) (+relu), strided/offset output for conv_t classes
#pragma unroll
    for (int i = 0; i < 4; i++) {
        int mo = blockIdx.x * BM + ty * 4 + i;
        if (mo >= p.Cout) break;
        float bi = __ldg(p.bias + mo);
#pragma unroll
        for (int j = 0; j < 4; j++) {
            int c2  = blockIdx.y * BN + tx * 4 + j;
            int n2  = c2 / OHOW; int rr = c2 - n2 * OHOW;
            int oy2 = rr / p.OW; int ox2 = rr - oy2 * p.OW;
            float v = acc[i][j] + bi;
            size_t oidx = ((size_t)(n2 * p.Cout + mo) * p.OHfull + (p.oyOff + oy2 * p.oyStep)) * p.OWfull
                        + p.oxOff + ox2 * p.oxStep;
            if (p.addRes) v += __ldg(p.residual + oidx);
            if (p.outRelu) v = fmaxf(v, 0.f);
            p.out[oidx] = v;
        }
    }
}

// ============================================================
// Dedicated conv_t2 (Cout=3): [16,128,128,128] -> [16,3,256,256]
// ============================================================
__global__ __launch_bounds__(256) void convt2_kernel(
    const float* __restrict__ in, const float* __restrict__ w,
    const float* __restrict__ bias, float* __restrict__ out)
{
    __shared__ float sw[3 * 128 * 16];  // [co][ci][4][4]
    const int tid = threadIdx.x;
    for (int i = tid; i < 6144; i += 256) sw[i] = w[i];
    __syncthreads();

    int idx = blockIdx.x * 256 + tid;              // over 16*256*256
    int ox = idx & 255;
    int oy = (idx >> 8) & 255;
    int n  = idx >> 16;
    int py = oy & 1, px = ox & 1;
    int iyb = ((oy + py) >> 1) - 1;                // taps iy = iyb + {0,1}
    int ixb = ((ox + px) >> 1) - 1;

    float acc0 = __ldg(bias + 0), acc1 = __ldg(bias + 1), acc2 = __ldg(bias + 2);
    const float* inb = in + (size_t)n * 128 * 128 * 128;

    for (int ci = 0; ci < 128; ci++) {
        const float* ic = inb + ci * 16384;
#pragma unroll
        for (int ty = 0; ty < 2; ty++) {
            int iy = iyb + ty;
            if ((unsigned)iy < 128u) {
#pragma unroll
                for (int tx2 = 0; tx2 < 2; tx2++) {
                    int ix = ixb + tx2;
                    if ((unsigned)ix < 128u) {
                        float v  = __ldg(ic + iy * 128 + ix);
                        int   wi = (py + 2 * ty) * 4 + (px + 2 * tx2);
                        acc0 = fmaf(v, sw[(0 * 128 + ci) * 16 + wi], acc0);
                        acc1 = fmaf(v, sw[(1 * 128 + ci) * 16 + wi], acc1);
                        acc2 = fmaf(v, sw[(2 * 128 + ci) * 16 + wi], acc2);
                    }
                }
            }
        }
    }
    size_t base = (size_t)n * 3 * 65536 + oy * 256 + ox;
    out[base]             = acc0;
    out[base + 65536]     = acc1;
    out[base + 2 * 65536] = acc2;
}

// ============================================================
// Residual VQ: all 4 levels fused, 1 thread = 1 spatial position
// ============================================================
#define VQ_NPOS 65536
#define VQ_SMEM_FLOATS (512 * 64 + 512 + 512 + 32)
#define VQ_SMEM_BYTES  (VQ_SMEM_FLOATS * 4)

__global__ __launch_bounds__(256) void vq_kernel(
    const float* __restrict__ z_e, const float* __restrict__ codebooks,
    float* __restrict__ z_q, float* __restrict__ partial, int* __restrict__ counts)
{
    extern __shared__ float sh[];
    float* cb    = sh;                       // 512*64
    float* cnorm = sh + 512 * 64;            // 512
    int*   hist  = (int*)(sh + 512 * 64 + 512);   // 512
    float* red   = sh + 512 * 64 + 512 + 512;     // 32

    const int tid = threadIdx.x;
    const int p   = blockIdx.x * 256 + tid;       // 0..65535
    const int n   = p >> 12;
    const int hw  = p & 4095;
    const float* zp = z_e + (size_t)n * 262144 + hw;   // stride 4096 per channel

    float r[64];
#pragma unroll
    for (int d = 0; d < 64; d++) r[d] = __ldg(zp + d * 4096);

    for (int level = 0; level < 4; level++) {
        // cooperative codebook load + hist zero
        const float4* src = (const float4*)(codebooks + (size_t)level * 512 * 64);
        float4* dst = (float4*)cb;
        for (int i = tid; i < 512 * 64 / 4; i += 256) dst[i] = src[i];
        hist[tid] = 0; hist[tid + 256] = 0;
        __syncthreads();
        for (int c = tid; c < 512; c += 256) {
            const float* cc = cb + c * 64;
            float s = 0.f;
#pragma unroll
            for (int d = 0; d < 64; d++) s = fmaf(cc[d], cc[d], s);
            cnorm[c] = s;
        }
        __syncthreads();

        // argmin over 512 codes (first-min, matching jnp.argmin)
        float best = 3.0e38f; int bidx = 0;
        for (int c = 0; c < 512; c++) {
            const float4* cc = (const float4*)(cb + (c << 6));
            float d0 = 0.f, d1 = 0.f, d2 = 0.f, d3 = 0.f;
#pragma unroll
            for (int i = 0; i < 16; i++) {
                float4 v = cc[i];
                d0 = fmaf(v.x, r[4 * i + 0], d0);
                d1 = fmaf(v.y, r[4 * i + 1], d1);
                d2 = fmaf(v.z, r[4 * i + 2], d2);
                d3 = fmaf(v.w, r[4 * i + 3], d3);
            }
            float score = cnorm[c] - 2.f * ((d0 + d1) + (d2 + d3));
            if (score < best) { best = score; bidx = c; }
        }
        atomicAdd(&hist[bidx], 1);

        // exact loss contribution + residual update
        const float* q = cb + (bidx << 6);
        float lsum = 0.f;
#pragma unroll
        for (int d = 0; d < 64; d++) {
            float diff = q[d] - r[d];
            lsum = fmaf(diff, diff, lsum);
            r[d] = -diff;                 // r - q
        }

        // deterministic block reduction of lsum
        float v = lsum;
#pragma unroll
        for (int o = 16; o > 0; o >>= 1) v += __shfl_xor_sync(0xffffffffu, v, o);
        if ((tid & 31) == 0) red[tid >> 5] = v;
        __syncthreads();
        if (tid == 0) {
            float t = 0.f;
            for (int i = 0; i < 8; i++) t += red[i];
            partial[blockIdx.x * 4 + level] = t;
        }
        // flush histogram
        atomicAdd(&counts[level * 512 + tid],       hist[tid]);
        atomicAdd(&counts[level * 512 + tid + 256], hist[tid + 256]);
        __syncthreads();
    }

    // z_q = z_e - final residual (telescoped q_sum)
    float* oq = z_q + (size_t)n * 262144 + hw;
#pragma unroll
    for (int d = 0; d < 64; d++) oq[d * 4096] = __ldg(zp + d * 4096) - r[d];
}

__global__ void vq_zero(float* partial, int* counts)
{
    int i = blockIdx.x * 256 + threadIdx.x;
    if (i < 1024) partial[i] = 0.f;
    if (i < 2048) counts[i]  = 0;
}

__global__ void vq_finalize(const float* __restrict__ partial, const int* __restrict__ counts,
                            float* __restrict__ out_loss, float* __restrict__ out_perp)
{
    __shared__ float losses[4];
    int tid = threadIdx.x;
    if (tid < 4) {
        float e = 0.f;
        for (int b = 0; b < 256; b++) e += partial[b * 4 + tid];
        e /= (65536.f * 64.f);
        losses[tid] = 0.25f * e;
        float s = 0.f;
        for (int c = 0; c < 512; c++) {
            float pr = (float)counts[tid * 512 + c] / 65536.f;
            s += pr * logf(pr + 1e-10f);
        }
        out_perp[tid] = expf(-s);
    }
    __syncthreads();
    if (tid == 0)
        out_loss[0] = 0.25f * (losses[0] + losses[1] + losses[2] + losses[3]);
}

// ============================================================
// Host-side launch helpers
// ============================================================
static void conv2d(const float* in, const float* w, const float* bias, const float* res,
                   float* out, int N, int Cin, int IH, int IW, int Cout, int OH, int OW,
                   int KH, int KW, int stride, int pad, bool inRelu, bool outRelu)
{
    ConvParams p;
    p.in = in; p.w = w; p.bias = bias; p.residual = res; p.out = out;
    p.N = N; p.Cin = Cin; p.IH = IH; p.IW = IW; p.Cout = Cout; p.OH = OH; p.OW = OW;
    p.KH = KH; p.KW = KW; p.KHW = KH * KW; p.Kdim = Cin * KH * KW;
    p.stride = stride; p.padH = pad; p.padW = pad;
    p.wsCo = Cin * KH * KW; p.wsCi = KH * KW; p.wsKy = KW;
    p.kyOff = 0; p.kyStep = 1; p.kxOff = 0; p.kxStep = 1;
    p.OHfull = OH; p.OWfull = OW; p.oyOff = 0; p.oyStep = 1; p.oxOff = 0; p.oxStep = 1;
    p.inRelu = inRelu ? 1 : 0; p.outRelu = outRelu ? 1 : 0; p.addRes = (res != nullptr) ? 1 : 0;
    dim3 grid((Cout + BM - 1) / BM, (N * OH * OW) / BN);
    conv_gemm<<<grid, 256>>>(p);
}

// ConvTranspose2d(k=4, s=2, p=1) as 4 parity-class stride-1 2x2 convs
static void convT(const float* in, const float* w, const float* bias, float* out,
                  int N, int Cin, int IH, int IW, int Cout, bool inRelu, bool outRelu)
{
    for (int py = 0; py < 2; py++)
        for (int px = 0; px < 2; px++) {
            ConvParams p;
            p.in = in; p.w = w; p.bias = bias; p.residual = nullptr; p.out = out;
            p.N = N; p.Cin = Cin; p.IH = IH; p.IW = IW; p.Cout = Cout; p.OH = IH; p.OW = IW;
            p.KH = 2; p.KW = 2; p.KHW = 4; p.Kdim = Cin * 4;
            p.stride = 1; p.padH = 1 - py; p.padW = 1 - px;
            p.wsCo = Cin * 16; p.wsCi = 16; p.wsKy = 4;
            p.kyOff = py; p.kyStep = 2; p.kxOff = px; p.kxStep = 2;
            p.OHfull = 2 * IH; p.OWfull = 2 * IW;
            p.oyOff = py; p.oyStep = 2; p.oxOff = px; p.oxStep = 2;
            p.inRelu = inRelu ? 1 : 0; p.outRelu = outRelu ? 1 : 0; p.addRes = 0;
            dim3 grid((Cout + BM - 1) / BM, (N * IH * IW) / BN);
            conv_gemm<<<grid, 256>>>(p);
        }
}

extern "C" void kernel_launch(void* const* d_in, const int* in_sizes, int n_in,
                              void* d_out, int out_size)
{
    (void)in_sizes; (void)n_in; (void)out_size;

    const float* x       = (const float*)d_in[0];
    const float* enc_w1  = (const float*)d_in[1];
    const float* enc_b1  = (const float*)d_in[2];
    const float* enc_w2  = (const float*)d_in[3];
    const float* enc_b2  = (const float*)d_in[4];
    const float* enc_w3  = (const float*)d_in[5];
    const float* enc_b3  = (const float*)d_in[6];
    const float* enc_rw1 = (const float*)d_in[7];
    const float* enc_rb1 = (const float*)d_in[8];
    const float* enc_rw2 = (const float*)d_in[9];
    const float* enc_rb2 = (const float*)d_in[10];
    const float* enc_wp  = (const float*)d_in[11];
    const float* enc_bp  = (const float*)d_in[12];
    const float* dec_w1  = (const float*)d_in[13];
    const float* dec_b1  = (const float*)d_in[14];
    const float* dec_rw1 = (const float*)d_in[15];
    const float* dec_rb1 = (const float*)d_in[16];
    const float* dec_rw2 = (const float*)d_in[17];
    const float* dec_rb2 = (const float*)d_in[18];
    const float* t1w     = (const float*)d_in[19];
    const float* t1b     = (const float*)d_in[20];
    const float* t2w     = (const float*)d_in[21];
    const float* t2b     = (const float*)d_in[22];
    const float* cbs     = (const float*)d_in[23];

    float *h1, *ga, *gb, *gmid, *gpart; int* gcnt;
    cudaGetSymbolAddress((void**)&h1,   g_h1);
    cudaGetSymbolAddress((void**)&ga,   g_a);
    cudaGetSymbolAddress((void**)&gb,   g_b);
    cudaGetSymbolAddress((void**)&gmid, g_mid);
    cudaGetSymbolAddress((void**)&gpart,g_part);
    cudaGetSymbolAddress((void**)&gcnt, g_cnt);

    float* out    = (float*)d_out;
    float* o_xrec = out + OFF_XREC;
    float* o_loss = out + OFF_LOSS;
    float* o_zq   = out + OFF_ZQ;
    float* o_ze   = out + OFF_ZE;
    float* o_perp = out + OFF_PERP;

    // ---------------- Encoder ----------------
    conv2d(x,  enc_w1, enc_b1, nullptr, h1, 16,   3, 256, 256, 128, 128, 128, 4, 4, 2, 1, false, true);
    conv2d(h1, enc_w2, enc_b2, nullptr, ga, 16, 128, 128, 128, 256,  64,  64, 4, 4, 2, 1, false, true);
    conv2d(ga, enc_w3, enc_b3, nullptr, gb, 16, 256,  64,  64, 256,  64,  64, 3, 3, 1, 1, false, false);
    // res block 0
    conv2d(gb,   enc_rw1,            enc_rb1,       nullptr, gmid, 16, 256, 64, 64,  32, 64, 64, 3, 3, 1, 1, true, false);
    conv2d(gmid, enc_rw2,            enc_rb2,       gb,      ga,   16,  32, 64, 64, 256, 64, 64, 1, 1, 1, 0, true, false);
    // res block 1
    conv2d(ga,   enc_rw1 + 73728,    enc_rb1 + 32,  nullptr, gmid, 16, 256, 64, 64,  32, 64, 64, 3, 3, 1, 1, true, false);
    conv2d(gmid, enc_rw2 + 8192,     enc_rb2 + 256, ga,      gb,   16,  32, 64, 64, 256, 64, 64, 1, 1, 1, 0, true, false);
    // projection (final res-stack relu folded into inRelu) -> z_e
    conv2d(gb, enc_wp, enc_bp, nullptr, o_ze, 16, 256, 64, 64, 64, 64, 64, 1, 1, 1, 0, true, false);

    // ---------------- Residual VQ ----------------
    vq_zero<<<8, 256>>>(gpart, gcnt);
    cudaFuncSetAttribute(vq_kernel, cudaFuncAttributeMaxDynamicSharedMemorySize, VQ_SMEM_BYTES);
    vq_kernel<<<VQ_NPOS / 256, 256, VQ_SMEM_BYTES>>>(o_ze, cbs, o_zq, gpart, gcnt);
    vq_finalize<<<1, 128>>>(gpart, gcnt, o_loss, o_perp);

    // ---------------- Decoder ----------------
    conv2d(o_zq, dec_w1, dec_b1, nullptr, ga, 16, 64, 64, 64, 256, 64, 64, 3, 3, 1, 1, false, false);
    // res block 0
    conv2d(ga,   dec_rw1,         dec_rb1,       nullptr, gmid, 16, 256, 64, 64,  32, 64, 64, 3, 3, 1, 1, true, false);
    conv2d(gmid, dec_rw2,         dec_rb2,       ga,      gb,   16,  32, 64, 64, 256, 64, 64, 1, 1, 1, 0, true, false);
    // res block 1
    conv2d(gb,   dec_rw1 + 73728, dec_rb1 + 32,  nullptr, gmid, 16, 256, 64, 64,  32, 64, 64, 3, 3, 1, 1, true, false);
    conv2d(gmid, dec_rw2 + 8192,  dec_rb2 + 256, gb,      ga,   16,  32, 64, 64, 256, 64, 64, 1, 1, 1, 0, true, false);
    // conv_t1 (final res-stack relu folded in) -> relu'd [16,128,128,128]
    convT(ga, t1w, t1b, h1, 16, 256, 64, 64, 128, true, true);
    // conv_t2 -> x_recon
    convt2_kernel<<<4096, 256>>>(h1, t2w, t2b, o_xrec);
}

// round 2
// speedup vs baseline: 1.4741x; 1.4741x over previous
#include <cuda_runtime.h>
#include <math.h>

// ============================================================
// Scratch (device globals -- no allocation allowed)
// ============================================================
__device__ float g_h1 [33554432];  // [16,128,128,128]
__device__ float g_a  [16777216];  // [16,256,64,64]
__device__ float g_b  [16777216];  // [16,256,64,64]
__device__ float g_mid[ 2097152];  // [16,32,64,64]
__device__ float g_wT [2304*256];  // transposed weights [K][Cout]
__device__ float g_part[256 * 4];
__device__ int   g_cnt [4 * 512];

// Output layout (tuple order): x_recon | rq_loss | z_q | z_e | perps
#define OFF_XREC 0
#define OFF_LOSS 3145728
#define OFF_ZQ   3145729
#define OFF_ZE   7340033
#define OFF_PERP 11534337

#define BK 8
#define KMAX 2304

struct ConvParams {
    const float* in; const float* bias; const float* residual; float* out;
    int Cin, IH, IW, Cout, OH, OW;
    int KHW, KW, Kdim;
    int stride, padH, padW;
    int OHfull, OWfull, oyOff, oyStep, oxOff, oxStep;
    int inRelu, outRelu, addRes;
};

// ============================================================
// Weight transpose: w (arbitrary tap strides) -> wT[k][Cout]
// ============================================================
__global__ void wtrans_kernel(const float* __restrict__ w, float* __restrict__ wT,
                              int Cout, int Kdim, int KHW, int KW,
                              int wsCo, int wsCi, int wsKy,
                              int kyOff, int kyStep, int kxOff, int kxStep)
{
    int idx = blockIdx.x * 256 + threadIdx.x;
    if (idx >= Kdim * Cout) return;
    int k = idx / Cout, m = idx - k * Cout;
    int ci = k / KHW, r2 = k - ci * KHW;
    int ky = r2 / KW, kx = r2 - ky * KW;
    wT[idx] = w[m * wsCo + ci * wsCi + (kyOff + ky * kyStep) * wsKy + kxOff + kx * kxStep];
}

// ============================================================
// Implicit-GEMM conv, double-buffered, exact tiling
// ============================================================
template<int BM, int BN, int TM, int TN>
__global__ __launch_bounds__(256) void conv_gemm2(ConvParams p, const float* __restrict__ wT)
{
    constexpr int ASEG = TM / 4;
    constexpr int BSEG = TN / 4;
    __shared__ float As[2][BK][BM + 4];
    __shared__ float Bs[2][BK][BN + 4];
    __shared__ int sBOff[KMAX];
    __shared__ int sKyx [KMAX];

    const int tid  = threadIdx.x;
    const int Kdim = p.Kdim;

    for (int k = tid; k < Kdim; k += 256) {
        int ci = k / p.KHW, r2 = k - ci * p.KHW;
        int ky = r2 / p.KW, kx = r2 - ky * p.KW;
        sBOff[k] = (ci * p.IH + ky) * p.IW + kx;
        sKyx[k]  = (ky << 16) | kx;
    }

    // loader roles: lk = k-row, ln4 = 4 consecutive cols / m's
    const int lk  = tid >> 5;
    const int ln4 = (tid & 31) << 2;
    const int OHOW = p.OH * p.OW;
    const int Cout = p.Cout;
    const int mBase = blockIdx.x * BM;

    // B-column precompute (4 cols per thread)
    int inB[4], iy0a[4], ix0a[4];
    {
        int colBase = blockIdx.y * BN + ln4;
#pragma unroll
        for (int j = 0; j < 4; j++) {
            int col = colBase + j;
            int n2 = col / OHOW; int rr = col - n2 * OHOW;
            int oy = rr / p.OW;  int ox = rr - oy * p.OW;
            int iy0 = oy * p.stride - p.padH;
            int ix0 = ox * p.stride - p.padW;
            iy0a[j] = iy0; ix0a[j] = ix0;
            inB[j]  = (n2 * p.Cin * p.IH + iy0) * p.IW + ix0;
        }
    }

    float acc[TM][TN];
#pragma unroll
    for (int i = 0; i < TM; i++)
#pragma unroll
        for (int j = 0; j < TN; j++) acc[i][j] = 0.f;

    float4 aR, bR;

    auto loadA = [&](int k0) {
        int kg = k0 + lk;
        if constexpr (BM == 128) {
            aR = *(const float4*)(wT + (size_t)kg * Cout + mBase + ln4);
        } else if constexpr (BM == 64) {
            const float2 t2 = *(const float2*)(wT + (size_t)kg * Cout + mBase + ((tid & 31) << 1));
            aR.x = t2.x; aR.y = t2.y;
        } else {
            aR.x = wT[(size_t)kg * Cout + mBase + (tid & 31)];
        }
    };
    auto loadB = [&](int k0) {
        int kg = k0 + lk;
        int off = sBOff[kg];
        int kyx = sKyx[kg];
        int ky = kyx >> 16, kx = kyx & 0xffff;
        float v[4];
#pragma unroll
        for (int j = 0; j < 4; j++) {
            int iy = iy0a[j] + ky, ix = ix0a[j] + kx;
            float t = 0.f;
            if ((unsigned)iy < (unsigned)p.IH && (unsigned)ix < (unsigned)p.IW) {
                t = __ldg(p.in + inB[j] + off);
                if (p.inRelu) t = fmaxf(t, 0.f);
            }
            v[j] = t;
        }
        bR = make_float4(v[0], v[1], v[2], v[3]);
    };
    auto store = [&](int buf) {
        if constexpr (BM == 128) {
            *(float4*)&As[buf][lk][ln4] = aR;
        } else if constexpr (BM == 64) {
            int m2 = (tid & 31) << 1;
            As[buf][lk][m2] = aR.x; As[buf][lk][m2 + 1] = aR.y;
        } else {
            As[buf][lk][tid & 31] = aR.x;
        }
        *(float4*)&Bs[buf][lk][ln4] = bR;
    };

    __syncthreads();          // tables ready
    loadA(0); loadB(0); store(0);
    __syncthreads();

    const int nkb = Kdim / BK;
    const int tym = tid / (BN / TN);
    const int txn = tid % (BN / TN);

    for (int kb = 0; kb < nkb; kb++) {
        int cur = kb & 1;
        if (kb + 1 < nkb) { loadA((kb + 1) * BK); loadB((kb + 1) * BK); }
#pragma unroll
        for (int kk = 0; kk < BK; kk++) {
            float a[TM], b[TN];
#pragma unroll
            for (int s = 0; s < ASEG; s++)
                *(float4*)&a[s * 4] = *(const float4*)&As[cur][kk][tym * 4 + s * 64];
#pragma unroll
            for (int u = 0; u < BSEG; u++)
                *(float4*)&b[u * 4] = *(const float4*)&Bs[cur][kk][txn * 4 + u * 64];
#pragma unroll
            for (int i = 0; i < TM; i++)
#pragma unroll
                for (int j = 0; j < TN; j++)
                    acc[i][j] = fmaf(a[i], b[j], acc[i][j]);
        }
        if (kb + 1 < nkb) store(cur ^ 1);
        __syncthreads();
    }

    // Epilogue
    int colNC[BSEG * 4], colRow[BSEG * 4];
#pragma unroll
    for (int u = 0; u < BSEG; u++)
#pragma unroll
        for (int j = 0; j < 4; j++) {
            int col = blockIdx.y * BN + txn * 4 + u * 64 + j;
            int n2 = col / OHOW; int rr = col - n2 * OHOW;
            int oy = rr / p.OW;  int ox = rr - oy * p.OW;
            colNC[u * 4 + j]  = n2 * Cout;
            colRow[u * 4 + j] = (p.oyOff + oy * p.oyStep) * p.OWfull + p.oxOff + ox * p.oxStep;
        }
    const size_t plane = (size_t)p.OHfull * p.OWfull;
#pragma unroll
    for (int s = 0; s < ASEG; s++)
#pragma unroll
        for (int i = 0; i < 4; i++) {
            int m = mBase + tym * 4 + s * 64 + i;
            float bi = __ldg(p.bias + m);
#pragma unroll
            for (int u = 0; u < BSEG; u++)
#pragma unroll
                for (int j = 0; j < 4; j++) {
                    float v = acc[s * 4 + i][u * 4 + j] + bi;
                    size_t oidx = (size_t)(colNC[u * 4 + j] + m) * plane + colRow[u * 4 + j];
                    if (p.addRes) v += __ldg(p.residual + oidx);
                    if (p.outRelu) v = fmaxf(v, 0.f);
                    p.out[oidx] = v;
                }
        }
}

// ============================================================
// Dedicated conv_t2 (Cout=3): [16,128,128,128] -> [16,3,256,256]
// ============================================================
__global__ __launch_bounds__(256) void convt2_kernel(
    const float* __restrict__ in, const float* __restrict__ w,
    const float* __restrict__ bias, float* __restrict__ out)
{
    __shared__ float sw[3 * 128 * 16];
    const int tid = threadIdx.x;
    for (int i = tid; i < 6144; i += 256) sw[i] = w[i];
    __syncthreads();

    int idx = blockIdx.x * 256 + tid;
    int ox = idx & 255;
    int oy = (idx >> 8) & 255;
    int n  = idx >> 16;
    int py = oy & 1, px = ox & 1;
    int iyb = ((oy + py) >> 1) - 1;
    int ixb = ((ox + px) >> 1) - 1;

    float acc0 = __ldg(bias + 0), acc1 = __ldg(bias + 1), acc2 = __ldg(bias + 2);
    const float* inb = in + (size_t)n * 128 * 128 * 128;

    for (int ci = 0; ci < 128; ci++) {
        const float* ic = inb + ci * 16384;
#pragma unroll
        for (int ty = 0; ty < 2; ty++) {
            int iy = iyb + ty;
            if ((unsigned)iy < 128u) {
#pragma unroll
                for (int tx2 = 0; tx2 < 2; tx2++) {
                    int ix = ixb + tx2;
                    if ((unsigned)ix < 128u) {
                        float v  = __ldg(ic + iy * 128 + ix);
                        int   wi = (py + 2 * ty) * 4 + (px + 2 * tx2);
                        acc0 = fmaf(v, sw[(0 * 128 + ci) * 16 + wi], acc0);
                        acc1 = fmaf(v, sw[(1 * 128 + ci) * 16 + wi], acc1);
                        acc2 = fmaf(v, sw[(2 * 128 + ci) * 16 + wi], acc2);
                    }
                }
            }
        }
    }
    size_t base = (size_t)n * 3 * 65536 + oy * 256 + ox;
    out[base]             = acc0;
    out[base + 65536]     = acc1;
    out[base + 2 * 65536] = acc2;
}

// ============================================================
// Residual VQ (unchanged from R1 -- verified correct)
// ============================================================
#define VQ_NPOS 65536
#define VQ_SMEM_FLOATS (512 * 64 + 512 + 512 + 32)
#define VQ_SMEM_BYTES  (VQ_SMEM_FLOATS * 4)

__global__ __launch_bounds__(256) void vq_kernel(
    const float* __restrict__ z_e, const float* __restrict__ codebooks,
    float* __restrict__ z_q, float* __restrict__ partial, int* __restrict__ counts)
{
    extern __shared__ float sh[];
    float* cb    = sh;
    float* cnorm = sh + 512 * 64;
    int*   hist  = (int*)(sh + 512 * 64 + 512);
    float* red   = sh + 512 * 64 + 512 + 512;

    const int tid = threadIdx.x;
    const int p   = blockIdx.x * 256 + tid;
    const int n   = p >> 12;
    const int hw  = p & 4095;
    const float* zp = z_e + (size_t)n * 262144 + hw;

    float r[64];
#pragma unroll
    for (int d = 0; d < 64; d++) r[d] = __ldg(zp + d * 4096);

    for (int level = 0; level < 4; level++) {
        const float4* src = (const float4*)(codebooks + (size_t)level * 512 * 64);
        float4* dst = (float4*)cb;
        for (int i = tid; i < 512 * 64 / 4; i += 256) dst[i] = src[i];
        hist[tid] = 0; hist[tid + 256] = 0;
        __syncthreads();
        for (int c = tid; c < 512; c += 256) {
            const float* cc = cb + c * 64;
            float s = 0.f;
#pragma unroll
            for (int d = 0; d < 64; d++) s = fmaf(cc[d], cc[d], s);
            cnorm[c] = s;
        }
        __syncthreads();

        float best = 3.0e38f; int bidx = 0;
        for (int c = 0; c < 512; c++) {
            const float4* cc = (const float4*)(cb + (c << 6));
            float d0 = 0.f, d1 = 0.f, d2 = 0.f, d3 = 0.f;
#pragma unroll
            for (int i = 0; i < 16; i++) {
                float4 v = cc[i];
                d0 = fmaf(v.x, r[4 * i + 0], d0);
                d1 = fmaf(v.y, r[4 * i + 1], d1);
                d2 = fmaf(v.z, r[4 * i + 2], d2);
                d3 = fmaf(v.w, r[4 * i + 3], d3);
            }
            float score = cnorm[c] - 2.f * ((d0 + d1) + (d2 + d3));
            if (score < best) { best = score; bidx = c; }
        }
        atomicAdd(&hist[bidx], 1);

        const float* q = cb + (bidx << 6);
        float lsum = 0.f;
#pragma unroll
        for (int d = 0; d < 64; d++) {
            float diff = q[d] - r[d];
            lsum = fmaf(diff, diff, lsum);
            r[d] = -diff;
        }

        float v = lsum;
#pragma unroll
        for (int o = 16; o > 0; o >>= 1) v += __shfl_xor_sync(0xffffffffu, v, o);
        if ((tid & 31) == 0) red[tid >> 5] = v;
        __syncthreads();
        if (tid == 0) {
            float t = 0.f;
            for (int i = 0; i < 8; i++) t += red[i];
            partial[blockIdx.x * 4 + level] = t;
        }
        atomicAdd(&counts[level * 512 + tid],       hist[tid]);
        atomicAdd(&counts[level * 512 + tid + 256], hist[tid + 256]);
        __syncthreads();
    }

    float* oq = z_q + (size_t)n * 262144 + hw;
#pragma unroll
    for (int d = 0; d < 64; d++) oq[d * 4096] = __ldg(zp + d * 4096) - r[d];
}

__global__ void vq_zero(float* partial, int* counts)
{
    int i = blockIdx.x * 256 + threadIdx.x;
    if (i < 1024) partial[i] = 0.f;
    if (i < 2048) counts[i]  = 0;
}

__global__ void vq_finalize(const float* __restrict__ partial, const int* __restrict__ counts,
                            float* __restrict__ out_loss, float* __restrict__ out_perp)
{
    __shared__ float losses[4];
    int tid = threadIdx.x;
    if (tid < 4) {
        float e = 0.f;
        for (int b = 0; b < 256; b++) e += partial[b * 4 + tid];
        e /= (65536.f * 64.f);
        losses[tid] = 0.25f * e;
        float s = 0.f;
        for (int c = 0; c < 512; c++) {
            float pr = (float)counts[tid * 512 + c] / 65536.f;
            s += pr * logf(pr + 1e-10f);
        }
        out_perp[tid] = expf(-s);
    }
    __syncthreads();
    if (tid == 0)
        out_loss[0] = 0.25f * (losses[0] + losses[1] + losses[2] + losses[3]);
}

// ============================================================
// Host-side launch helpers
// ============================================================
static float* s_wT = nullptr;

static void launch_conv(int cfg, ConvParams& p, const float* wT, int gx, int gy)
{
    dim3 g(gx, gy);
    if (cfg == 0)      conv_gemm2<128, 128, 8, 8><<<g, 256>>>(p, wT);
    else if (cfg == 1) conv_gemm2< 64, 128, 4, 8><<<g, 256>>>(p, wT);
    else               conv_gemm2< 32, 128, 4, 4><<<g, 256>>>(p, wT);
}

static void conv2d(int cfg, const float* in, const float* w, const float* bias, const float* res,
                   float* out, int N, int Cin, int IH, int IW, int Cout, int OH, int OW,
                   int KH, int KW, int stride, int pad, bool inRelu, bool outRelu)
{
    int Kdim = Cin * KH * KW;
    wtrans_kernel<<<(Kdim * Cout + 255) / 256, 256>>>(
        w, s_wT, Cout, Kdim, KH * KW, KW,
        Cin * KH * KW, KH * KW, KW, 0, 1, 0, 1);

    ConvParams p;
    p.in = in; p.bias = bias; p.residual = res; p.out = out;
    p.Cin = Cin; p.IH = IH; p.IW = IW; p.Cout = Cout; p.OH = OH; p.OW = OW;
    p.KHW = KH * KW; p.KW = KW; p.Kdim = Kdim;
    p.stride = stride; p.padH = pad; p.padW = pad;
    p.OHfull = OH; p.OWfull = OW; p.oyOff = 0; p.oyStep = 1; p.oxOff = 0; p.oxStep = 1;
    p.inRelu = inRelu ? 1 : 0; p.outRelu = outRelu ? 1 : 0; p.addRes = (res != nullptr) ? 1 : 0;

    int BMsel = (cfg == 0) ? 128 : (cfg == 1) ? 64 : 32;
    launch_conv(cfg, p, s_wT, Cout / BMsel, (N * OH * OW) / 128);
}

// ConvTranspose2d(k=4,s=2,p=1) as 4 parity-class stride-1 2x2 convs
static void convT(const float* in, const float* w, const float* bias, float* out,
                  int N, int Cin, int IH, int IW, int Cout, bool inRelu, bool outRelu)
{
    int Kdim = Cin * 4;
    for (int py = 0; py < 2; py++)
        for (int px = 0; px < 2; px++) {
            float* wT = s_wT + (py * 2 + px) * Kdim * Cout;
            wtrans_kernel<<<(Kdim * Cout + 255) / 256, 256>>>(
                w, wT, Cout, Kdim, 4, 2,
                Cin * 16, 16, 4, py, 2, px, 2);

            ConvParams p;
            p.in = in; p.bias = bias; p.residual = nullptr; p.out = out;
            p.Cin = Cin; p.IH = IH; p.IW = IW; p.Cout = Cout; p.OH = IH; p.OW = IW;
            p.KHW = 4; p.KW = 2; p.Kdim = Kdim;
            p.stride = 1; p.padH = 1 - py; p.padW = 1 - px;
            p.OHfull = 2 * IH; p.OWfull = 2 * IW;
            p.oyOff = py; p.oyStep = 2; p.oxOff = px; p.oxStep = 2;
            p.inRelu = inRelu ? 1 : 0; p.outRelu = outRelu ? 1 : 0; p.addRes = 0;
            launch_conv(0, p, wT, Cout / 128, (N * IH * IW) / 128);
        }
}

extern "C" void kernel_launch(void* const* d_in, const int* in_sizes, int n_in,
                              void* d_out, int out_size)
{
    (void)in_sizes; (void)n_in; (void)out_size;

    const float* x       = (const float*)d_in[0];
    const float* enc_w1  = (const float*)d_in[1];
    const float* enc_b1  = (const float*)d_in[2];
    const float* enc_w2  = (const float*)d_in[3];
    const float* enc_b2  = (const float*)d_in[4];
    const float* enc_w3  = (const float*)d_in[5];
    const float* enc_b3  = (const float*)d_in[6];
    const float* enc_rw1 = (const float*)d_in[7];
    const float* enc_rb1 = (const float*)d_in[8];
    const float* enc_rw2 = (const float*)d_in[9];
    const float* enc_rb2 = (const float*)d_in[10];
    const float* enc_wp  = (const float*)d_in[11];
    const float* enc_bp  = (const float*)d_in[12];
    const float* dec_w1  = (const float*)d_in[13];
    const float* dec_b1  = (const float*)d_in[14];
    const float* dec_rw1 = (const float*)d_in[15];
    const float* dec_rb1 = (const float*)d_in[16];
    const float* dec_rw2 = (const float*)d_in[17];
    const float* dec_rb2 = (const float*)d_in[18];
    const float* t1w     = (const float*)d_in[19];
    const float* t1b     = (const float*)d_in[20];
    const float* t2w     = (const float*)d_in[21];
    const float* t2b     = (const float*)d_in[22];
    const float* cbs     = (const float*)d_in[23];

    float *h1, *ga, *gb, *gmid, *gpart; int* gcnt;
    cudaGetSymbolAddress((void**)&h1,    g_h1);
    cudaGetSymbolAddress((void**)&ga,    g_a);
    cudaGetSymbolAddress((void**)&gb,    g_b);
    cudaGetSymbolAddress((void**)&gmid,  g_mid);
    cudaGetSymbolAddress((void**)&s_wT,  g_wT);
    cudaGetSymbolAddress((void**)&gpart, g_part);
    cudaGetSymbolAddress((void**)&gcnt,  g_cnt);

    float* out    = (float*)d_out;
    float* o_xrec = out + OFF_XREC;
    float* o_loss = out + OFF_LOSS;
    float* o_zq   = out + OFF_ZQ;
    float* o_ze   = out + OFF_ZE;
    float* o_perp = out + OFF_PERP;

    // ---------------- Encoder ----------------
    conv2d(0, x,  enc_w1, enc_b1, nullptr, h1, 16,   3, 256, 256, 128, 128, 128, 4, 4, 2, 1, false, true);
    conv2d(0, h1, enc_w2, enc_b2, nullptr, ga, 16, 128, 128, 128, 256,  64,  64, 4, 4, 2, 1, false, true);
    conv2d(0, ga, enc_w3, enc_b3, nullptr, gb, 16, 256,  64,  64, 256,  64,  64, 3, 3, 1, 1, false, false);
    // res block 0
    conv2d(2, gb,   enc_rw1,         enc_rb1,       nullptr, gmid, 16, 256, 64, 64,  32, 64, 64, 3, 3, 1, 1, true, false);
    conv2d(0, gmid, enc_rw2,         enc_rb2,       gb,      ga,   16,  32, 64, 64, 256, 64, 64, 1, 1, 1, 0, true, false);
    // res block 1
    conv2d(2, ga,   enc_rw1 + 73728, enc_rb1 + 32,  nullptr, gmid, 16, 256, 64, 64,  32, 64, 64, 3, 3, 1, 1, true, false);
    conv2d(0, gmid, enc_rw2 + 8192,  enc_rb2 + 256, ga,      gb,   16,  32, 64, 64, 256, 64, 64, 1, 1, 1, 0, true, false);
    // projection (final res-stack relu folded into inRelu) -> z_e
    conv2d(1, gb, enc_wp, enc_bp, nullptr, o_ze, 16, 256, 64, 64, 64, 64, 64, 1, 1, 1, 0, true, false);

    // ---------------- Residual VQ ----------------
    vq_zero<<<8, 256>>>(gpart, gcnt);
    cudaFuncSetAttribute(vq_kernel, cudaFuncAttributeMaxDynamicSharedMemorySize, VQ_SMEM_BYTES);
    vq_kernel<<<VQ_NPOS / 256, 256, VQ_SMEM_BYTES>>>(o_ze, cbs, o_zq, gpart, gcnt);
    vq_finalize<<<1, 128>>>(gpart, gcnt, o_loss, o_perp);

    // ---------------- Decoder ----------------
    conv2d(0, o_zq, dec_w1, dec_b1, nullptr, ga, 16, 64, 64, 64, 256, 64, 64, 3, 3, 1, 1, false, false);
    // res block 0
    conv2d(2, ga,   dec_rw1,         dec_rb1,       nullptr, gmid, 16, 256, 64, 64,  32, 64, 64, 3, 3, 1, 1, true, false);
    conv2d(0, gmid, dec_rw2,         dec_rb2,       ga,      gb,   16,  32, 64, 64, 256, 64, 64, 1, 1, 1, 0, true, false);
    // res block 1
    conv2d(2, gb,   dec_rw1 + 73728, dec_rb1 + 32,  nullptr, gmid, 16, 256, 64, 64,  32, 64, 64, 3, 3, 1, 1, true, false);
    conv2d(0, gmid, dec_rw2 + 8192,  dec_rb2 + 256, gb,      ga,   16,  32, 64, 64, 256, 64, 64, 1, 1, 1, 0, true, false);
    // conv_t1 (final res-stack relu folded in) -> relu'd [16,128,128,128]
    convT(ga, t1w, t1b, h1, 16, 256, 64, 64, 128, true, true);
    // conv_t2 -> x_recon
    convt2_kernel<<<4096, 256>>>(h1, t2w, t2b, o_xrec);
}

// round 3
// speedup vs baseline: 1.4761x; 1.0013x over previous
#include <cuda_runtime.h>
#include <math.h>

// ============================================================
// Scratch (device globals -- no allocation allowed)
// ============================================================
__device__ float g_h1 [33554432];  // [16,128,128,128]
__device__ float g_a  [16777216];  // [16,256,64,64]
__device__ float g_b  [16777216];  // [16,256,64,64]
__device__ float g_mid[ 2097152];  // [16,32,64,64]
__device__ float g_wT [2304*256];  // transposed weights [K][Cout]
__device__ float g_part[256 * 4];
__device__ int   g_cnt [4 * 512];

// Output layout (tuple order): x_recon | rq_loss | z_q | z_e | perps
#define OFF_XREC 0
#define OFF_LOSS 3145728
#define OFF_ZQ   3145729
#define OFF_ZE   7340033
#define OFF_PERP 11534337

#define BK 8
#define KMAX 2304

struct ConvParams {
    const float* in; const float* bias; const float* residual; float* out;
    int Cin, IH, IW, Cout, OH, OW;
    int KHW, KW, Kdim;
    int stride, padH, padW;
    int OHfull, OWfull, oyOff, oyStep, oxOff, oxStep;
    int inRelu, outRelu, addRes;
};

// ============================================================
// Weight transpose: w (arbitrary tap strides) -> wT[k][Cout]
// ============================================================
__global__ void wtrans_kernel(const float* __restrict__ w, float* __restrict__ wT,
                              int Cout, int Kdim, int KHW, int KW,
                              int wsCo, int wsCi, int wsKy,
                              int kyOff, int kyStep, int kxOff, int kxStep)
{
    int idx = blockIdx.x * 256 + threadIdx.x;
    if (idx >= Kdim * Cout) return;
    int k = idx / Cout, m = idx - k * Cout;
    int ci = k / KHW, r2 = k - ci * KHW;
    int ky = r2 / KW, kx = r2 - ky * KW;
    wT[idx] = w[m * wsCo + ci * wsCi + (kyOff + ky * kyStep) * wsKy + kxOff + kx * kxStep];
}

// ============================================================
// Implicit-GEMM conv, double-buffered, exact tiling
// ============================================================
template<int BM, int BN, int TM, int TN>
__global__ __launch_bounds__(256) void conv_gemm2(ConvParams p, const float* __restrict__ wT)
{
    constexpr int ASEG = TM / 4;
    constexpr int BSEG = TN / 4;
    __shared__ float As[2][BK][BM + 4];
    __shared__ float Bs[2][BK][BN + 4];
    __shared__ int sBOff[KMAX];
    __shared__ int sKyx [KMAX];

    const int tid  = threadIdx.x;
    const int Kdim = p.Kdim;

    for (int k = tid; k < Kdim; k += 256) {
        int ci = k / p.KHW, r2 = k - ci * p.KHW;
        int ky = r2 / p.KW, kx = r2 - ky * p.KW;
        sBOff[k] = (ci * p.IH + ky) * p.IW + kx;
        sKyx[k]  = (ky << 16) | kx;
    }

    // loader roles: lk = k-row, ln4 = 4 consecutive cols / m's
    const int lk  = tid >> 5;
    const int ln4 = (tid & 31) << 2;
    const int OHOW = p.OH * p.OW;
    const int Cout = p.Cout;
    const int mBase = blockIdx.x * BM;

    // B-column precompute (4 cols per thread)
    int inB[4], iy0a[4], ix0a[4];
    {
        int colBase = blockIdx.y * BN + ln4;
#pragma unroll
        for (int j = 0; j < 4; j++) {
            int col = colBase + j;
            int n2 = col / OHOW; int rr = col - n2 * OHOW;
            int oy = rr / p.OW;  int ox = rr - oy * p.OW;
            int iy0 = oy * p.stride - p.padH;
            int ix0 = ox * p.stride - p.padW;
            iy0a[j] = iy0; ix0a[j] = ix0;
            inB[j]  = (n2 * p.Cin * p.IH + iy0) * p.IW + ix0;
        }
    }

    float acc[TM][TN];
#pragma unroll
    for (int i = 0; i < TM; i++)
#pragma unroll
        for (int j = 0; j < TN; j++) acc[i][j] = 0.f;

    float4 aR, bR;

    auto loadA = [&](int k0) {
        int kg = k0 + lk;
        if constexpr (BM == 128) {
            aR = *(const float4*)(wT + (size_t)kg * Cout + mBase + ln4);
        } else if constexpr (BM == 64) {
            const float2 t2 = *(const float2*)(wT + (size_t)kg * Cout + mBase + ((tid & 31) << 1));
            aR.x = t2.x; aR.y = t2.y;
        } else {
            aR.x = wT[(size_t)kg * Cout + mBase + (tid & 31)];
        }
    };
    auto loadB = [&](int k0) {
        int kg = k0 + lk;
        int off = sBOff[kg];
        int kyx = sKyx[kg];
        int ky = kyx >> 16, kx = kyx & 0xffff;
        float v[4];
#pragma unroll
        for (int j = 0; j < 4; j++) {
            int iy = iy0a[j] + ky, ix = ix0a[j] + kx;
            float t = 0.f;
            if ((unsigned)iy < (unsigned)p.IH && (unsigned)ix < (unsigned)p.IW) {
                t = __ldg(p.in + inB[j] + off);
                if (p.inRelu) t = fmaxf(t, 0.f);
            }
            v[j] = t;
        }
        bR = make_float4(v[0], v[1], v[2], v[3]);
    };
    auto store = [&](int buf) {
        if constexpr (BM == 128) {
            *(float4*)&As[buf][lk][ln4] = aR;
        } else if constexpr (BM == 64) {
            int m2 = (tid & 31) << 1;
            As[buf][lk][m2] = aR.x; As[buf][lk][m2 + 1] = aR.y;
        } else {
            As[buf][lk][tid & 31] = aR.x;
        }
        *(float4*)&Bs[buf][lk][ln4] = bR;
    };

    __syncthreads();          // tables ready
    loadA(0); loadB(0); store(0);
    __syncthreads();

    const int nkb = Kdim / BK;
    const int tym = tid / (BN / TN);
    const int txn = tid % (BN / TN);

    for (int kb = 0; kb < nkb; kb++) {
        int cur = kb & 1;
        if (kb + 1 < nkb) { loadA((kb + 1) * BK); loadB((kb + 1) * BK); }
#pragma unroll
        for (int kk = 0; kk < BK; kk++) {
            float a[TM], b[TN];
#pragma unroll
            for (int s = 0; s < ASEG; s++)
                *(float4*)&a[s * 4] = *(const float4*)&As[cur][kk][tym * 4 + s * 64];
#pragma unroll
            for (int u = 0; u < BSEG; u++)
                *(float4*)&b[u * 4] = *(const float4*)&Bs[cur][kk][txn * 4 + u * 64];
#pragma unroll
            for (int i = 0; i < TM; i++)
#pragma unroll
                for (int j = 0; j < TN; j++)
                    acc[i][j] = fmaf(a[i], b[j], acc[i][j]);
        }
        if (kb + 1 < nkb) store(cur ^ 1);
        __syncthreads();
    }

    // Epilogue
    int colNC[BSEG * 4], colRow[BSEG * 4];
#pragma unroll
    for (int u = 0; u < BSEG; u++)
#pragma unroll
        for (int j = 0; j < 4; j++) {
            int col = blockIdx.y * BN + txn * 4 + u * 64 + j;
            int n2 = col / OHOW; int rr = col - n2 * OHOW;
            int oy = rr / p.OW;  int ox = rr - oy * p.OW;
            colNC[u * 4 + j]  = n2 * Cout;
            colRow[u * 4 + j] = (p.oyOff + oy * p.oyStep) * p.OWfull + p.oxOff + ox * p.oxStep;
        }
    const size_t plane = (size_t)p.OHfull * p.OWfull;
#pragma unroll
    for (int s = 0; s < ASEG; s++)
#pragma unroll
        for (int i = 0; i < 4; i++) {
            int m = mBase + tym * 4 + s * 64 + i;
            float bi = __ldg(p.bias + m);
#pragma unroll
            for (int u = 0; u < BSEG; u++)
#pragma unroll
                for (int j = 0; j < 4; j++) {
                    float v = acc[s * 4 + i][u * 4 + j] + bi;
                    size_t oidx = (size_t)(colNC[u * 4 + j] + m) * plane + colRow[u * 4 + j];
                    if (p.addRes) v += __ldg(p.residual + oidx);
                    if (p.outRelu) v = fmaxf(v, 0.f);
                    p.out[oidx] = v;
                }
        }
}

// ============================================================
// Dedicated conv_t2 (Cout=3): [16,128,128,128] -> [16,3,256,256]
// ============================================================
__global__ __launch_bounds__(256) void convt2_kernel(
    const float* __restrict__ in, const float* __restrict__ w,
    const float* __restrict__ bias, float* __restrict__ out)
{
    __shared__ float sw[3 * 128 * 16];
    const int tid = threadIdx.x;
    for (int i = tid; i < 6144; i += 256) sw[i] = w[i];
    __syncthreads();

    int idx = blockIdx.x * 256 + tid;
    int ox = idx & 255;
    int oy = (idx >> 8) & 255;
    int n  = idx >> 16;
    int py = oy & 1, px = ox & 1;
    int iyb = ((oy + py) >> 1) - 1;
    int ixb = ((ox + px) >> 1) - 1;

    float acc0 = __ldg(bias + 0), acc1 = __ldg(bias + 1), acc2 = __ldg(bias + 2);
    const float* inb = in + (size_t)n * 128 * 128 * 128;

    for (int ci = 0; ci < 128; ci++) {
        const float* ic = inb + ci * 16384;
#pragma unroll
        for (int ty = 0; ty < 2; ty++) {
            int iy = iyb + ty;
            if ((unsigned)iy < 128u) {
#pragma unroll
                for (int tx2 = 0; tx2 < 2; tx2++) {
                    int ix = ixb + tx2;
                    if ((unsigned)ix < 128u) {
                        float v  = __ldg(ic + iy * 128 + ix);
                        int   wi = (py + 2 * ty) * 4 + (px + 2 * tx2);
                        acc0 = fmaf(v, sw[(0 * 128 + ci) * 16 + wi], acc0);
                        acc1 = fmaf(v, sw[(1 * 128 + ci) * 16 + wi], acc1);
                        acc2 = fmaf(v, sw[(2 * 128 + ci) * 16 + wi], acc2);
                    }
                }
            }
        }
    }
    size_t base = (size_t)n * 3 * 65536 + oy * 256 + ox;
    out[base]             = acc0;
    out[base + 65536]     = acc1;
    out[base + 2 * 65536] = acc2;
}

// ============================================================
// Residual VQ (unchanged from R1 -- verified correct)
// ============================================================
#define VQ_NPOS 65536
#define VQ_SMEM_FLOATS (512 * 64 + 512 + 512 + 32)
#define VQ_SMEM_BYTES  (VQ_SMEM_FLOATS * 4)

__global__ __launch_bounds__(256) void vq_kernel(
    const float* __restrict__ z_e, const float* __restrict__ codebooks,
    float* __restrict__ z_q, float* __restrict__ partial, int* __restrict__ counts)
{
    extern __shared__ float sh[];
    float* cb    = sh;
    float* cnorm = sh + 512 * 64;
    int*   hist  = (int*)(sh + 512 * 64 + 512);
    float* red   = sh + 512 * 64 + 512 + 512;

    const int tid = threadIdx.x;
    const int p   = blockIdx.x * 256 + tid;
    const int n   = p >> 12;
    const int hw  = p & 4095;
    const float* zp = z_e + (size_t)n * 262144 + hw;

    float r[64];
#pragma unroll
    for (int d = 0; d < 64; d++) r[d] = __ldg(zp + d * 4096);

    for (int level = 0; level < 4; level++) {
        const float4* src = (const float4*)(codebooks + (size_t)level * 512 * 64);
        float4* dst = (float4*)cb;
        for (int i = tid; i < 512 * 64 / 4; i += 256) dst[i] = src[i];
        hist[tid] = 0; hist[tid + 256] = 0;
        __syncthreads();
        for (int c = tid; c < 512; c += 256) {
            const float* cc = cb + c * 64;
            float s = 0.f;
#pragma unroll
            for (int d = 0; d < 64; d++) s = fmaf(cc[d], cc[d], s);
            cnorm[c] = s;
        }
        __syncthreads();

        float best = 3.0e38f; int bidx = 0;
        for (int c = 0; c < 512; c++) {
            const float4* cc = (const float4*)(cb + (c << 6));
            float d0 = 0.f, d1 = 0.f, d2 = 0.f, d3 = 0.f;
#pragma unroll
            for (int i = 0; i < 16; i++) {
                float4 v = cc[i];
                d0 = fmaf(v.x, r[4 * i + 0], d0);
                d1 = fmaf(v.y, r[4 * i + 1], d1);
                d2 = fmaf(v.z, r[4 * i + 2], d2);
                d3 = fmaf(v.w, r[4 * i + 3], d3);
            }
            float score = cnorm[c] - 2.f * ((d0 + d1) + (d2 + d3));
            if (score < best) { best = score; bidx = c; }
        }
        atomicAdd(&hist[bidx], 1);

        const float* q = cb + (bidx << 6);
        float lsum = 0.f;
#pragma unroll
        for (int d = 0; d < 64; d++) {
            float diff = q[d] - r[d];
            lsum = fmaf(diff, diff, lsum);
            r[d] = -diff;
        }

        float v = lsum;
#pragma unroll
        for (int o = 16; o > 0; o >>= 1) v += __shfl_xor_sync(0xffffffffu, v, o);
        if ((tid & 31) == 0) red[tid >> 5] = v;
        __syncthreads();
        if (tid == 0) {
            float t = 0.f;
            for (int i = 0; i < 8; i++) t += red[i];
            partial[blockIdx.x * 4 + level] = t;
        }
        atomicAdd(&counts[level * 512 + tid],       hist[tid]);
        atomicAdd(&counts[level * 512 + tid + 256], hist[tid + 256]);
        __syncthreads();
    }

    float* oq = z_q + (size_t)n * 262144 + hw;
#pragma unroll
    for (int d = 0; d < 64; d++) oq[d * 4096] = __ldg(zp + d * 4096) - r[d];
}

__global__ void vq_zero(float* partial, int* counts)
{
    int i = blockIdx.x * 256 + threadIdx.x;
    if (i < 1024) partial[i] = 0.f;
    if (i < 2048) counts[i]  = 0;
}

__global__ void vq_finalize(const float* __restrict__ partial, const int* __restrict__ counts,
                            float* __restrict__ out_loss, float* __restrict__ out_perp)
{
    __shared__ float losses[4];
    int tid = threadIdx.x;
    if (tid < 4) {
        float e = 0.f;
        for (int b = 0; b < 256; b++) e += partial[b * 4 + tid];
        e /= (65536.f * 64.f);
        losses[tid] = 0.25f * e;
        float s = 0.f;
        for (int c = 0; c < 512; c++) {
            float pr = (float)counts[tid * 512 + c] / 65536.f;
            s += pr * logf(pr + 1e-10f);
        }
        out_perp[tid] = expf(-s);
    }
    __syncthreads();
    if (tid == 0)
        out_loss[0] = 0.25f * (losses[0] + losses[1] + losses[2] + losses[3]);
}

// ============================================================
// Host-side launch helpers
// ============================================================
static float* s_wT = nullptr;

static void launch_conv(int cfg, ConvParams& p, const float* wT, int gx, int gy)
{
    dim3 g(gx, gy);
    if (cfg == 0)      conv_gemm2<128, 128, 8, 8><<<g, 256>>>(p, wT);
    else if (cfg == 1) conv_gemm2< 64, 128, 4, 8><<<g, 256>>>(p, wT);
    else               conv_gemm2< 32, 128, 4, 4><<<g, 256>>>(p, wT);
}

static void conv2d(int cfg, const float* in, const float* w, const float* bias, const float* res,
                   float* out, int N, int Cin, int IH, int IW, int Cout, int OH, int OW,
                   int KH, int KW, int stride, int pad, bool inRelu, bool outRelu)
{
    int Kdim = Cin * KH * KW;
    wtrans_kernel<<<(Kdim * Cout + 255) / 256, 256>>>(
        w, s_wT, Cout, Kdim, KH * KW, KW,
        Cin * KH * KW, KH * KW, KW, 0, 1, 0, 1);

    ConvParams p;
    p.in = in; p.bias = bias; p.residual = res; p.out = out;
    p.Cin = Cin; p.IH = IH; p.IW = IW; p.Cout = Cout; p.OH = OH; p.OW = OW;
    p.KHW = KH * KW; p.KW = KW; p.Kdim = Kdim;
    p.stride = stride; p.padH = pad; p.padW = pad;
    p.OHfull = OH; p.OWfull = OW; p.oyOff = 0; p.oyStep = 1; p.oxOff = 0; p.oxStep = 1;
    p.inRelu = inRelu ? 1 : 0; p.outRelu = outRelu ? 1 : 0; p.addRes = (res != nullptr) ? 1 : 0;

    int BMsel = (cfg == 0) ? 128 : (cfg == 1) ? 64 : 32;
    launch_conv(cfg, p, s_wT, Cout / BMsel, (N * OH * OW) / 128);
}

// ConvTranspose2d(k=4,s=2,p=1) as 4 parity-class stride-1 2x2 convs
static void convT(const float* in, const float* w, const float* bias, float* out,
                  int N, int Cin, int IH, int IW, int Cout, bool inRelu, bool outRelu)
{
    int Kdim = Cin * 4;
    for (int py = 0; py < 2; py++)
        for (int px = 0; px < 2; px++) {
            float* wT = s_wT + (py * 2 + px) * Kdim * Cout;
            wtrans_kernel<<<(Kdim * Cout + 255) / 256, 256>>>(
                w, wT, Cout, Kdim, 4, 2,
                Cin * 16, 16, 4, py, 2, px, 2);

            ConvParams p;
            p.in = in; p.bias = bias; p.residual = nullptr; p.out = out;
            p.Cin = Cin; p.IH = IH; p.IW = IW; p.Cout = Cout; p.OH = IH; p.OW = IW;
            p.KHW = 4; p.KW = 2; p.Kdim = Kdim;
            p.stride = 1; p.padH = 1 - py; p.padW = 1 - px;
            p.OHfull = 2 * IH; p.OWfull = 2 * IW;
            p.oyOff = py; p.oyStep = 2; p.oxOff = px; p.oxStep = 2;
            p.inRelu = inRelu ? 1 : 0; p.outRelu = outRelu ? 1 : 0; p.addRes = 0;
            launch_conv(0, p, wT, Cout / 128, (N * IH * IW) / 128);
        }
}

extern "C" void kernel_launch(void* const* d_in, const int* in_sizes, int n_in,
                              void* d_out, int out_size)
{
    (void)in_sizes; (void)n_in; (void)out_size;

    const float* x       = (const float*)d_in[0];
    const float* enc_w1  = (const float*)d_in[1];
    const float* enc_b1  = (const float*)d_in[2];
    const float* enc_w2  = (const float*)d_in[3];
    const float* enc_b2  = (const float*)d_in[4];
    const float* enc_w3  = (const float*)d_in[5];
    const float* enc_b3  = (const float*)d_in[6];
    const float* enc_rw1 = (const float*)d_in[7];
    const float* enc_rb1 = (const float*)d_in[8];
    const float* enc_rw2 = (const float*)d_in[9];
    const float* enc_rb2 = (const float*)d_in[10];
    const float* enc_wp  = (const float*)d_in[11];
    const float* enc_bp  = (const float*)d_in[12];
    const float* dec_w1  = (const float*)d_in[13];
    const float* dec_b1  = (const float*)d_in[14];
    const float* dec_rw1 = (const float*)d_in[15];
    const float* dec_rb1 = (const float*)d_in[16];
    const float* dec_rw2 = (const float*)d_in[17];
    const float* dec_rb2 = (const float*)d_in[18];
    const float* t1w     = (const float*)d_in[19];
    const float* t1b     = (const float*)d_in[20];
    const float* t2w     = (const float*)d_in[21];
    const float* t2b     = (const float*)d_in[22];
    const float* cbs     = (const float*)d_in[23];

    float *h1, *ga, *gb, *gmid, *gpart; int* gcnt;
    cudaGetSymbolAddress((void**)&h1,    g_h1);
    cudaGetSymbolAddress((void**)&ga,    g_a);
    cudaGetSymbolAddress((void**)&gb,    g_b);
    cudaGetSymbolAddress((void**)&gmid,  g_mid);
    cudaGetSymbolAddress((void**)&s_wT,  g_wT);
    cudaGetSymbolAddress((void**)&gpart, g_part);
    cudaGetSymbolAddress((void**)&gcnt,  g_cnt);

    float* out    = (float*)d_out;
    float* o_xrec = out + OFF_XREC;
    float* o_loss = out + OFF_LOSS;
    float* o_zq   = out + OFF_ZQ;
    float* o_ze   = out + OFF_ZE;
    float* o_perp = out + OFF_PERP;

    // ---------------- Encoder ----------------
    conv2d(0, x,  enc_w1, enc_b1, nullptr, h1, 16,   3, 256, 256, 128, 128, 128, 4, 4, 2, 1, false, true);
    conv2d(0, h1, enc_w2, enc_b2, nullptr, ga, 16, 128, 128, 128, 256,  64,  64, 4, 4, 2, 1, false, true);
    conv2d(0, ga, enc_w3, enc_b3, nullptr, gb, 16, 256,  64,  64, 256,  64,  64, 3, 3, 1, 1, false, false);
    // res block 0
    conv2d(2, gb,   enc_rw1,         enc_rb1,       nullptr, gmid, 16, 256, 64, 64,  32, 64, 64, 3, 3, 1, 1, true, false);
    conv2d(0, gmid, enc_rw2,         enc_rb2,       gb,      ga,   16,  32, 64, 64, 256, 64, 64, 1, 1, 1, 0, true, false);
    // res block 1
    conv2d(2, ga,   enc_rw1 + 73728, enc_rb1 + 32,  nullptr, gmid, 16, 256, 64, 64,  32, 64, 64, 3, 3, 1, 1, true, false);
    conv2d(0, gmid, enc_rw2 + 8192,  enc_rb2 + 256, ga,      gb,   16,  32, 64, 64, 256, 64, 64, 1, 1, 1, 0, true, false);
    // projection (final res-stack relu folded into inRelu) -> z_e
    conv2d(1, gb, enc_wp, enc_bp, nullptr, o_ze, 16, 256, 64, 64, 64, 64, 64, 1, 1, 1, 0, true, false);

    // ---------------- Residual VQ ----------------
    vq_zero<<<8, 256>>>(gpart, gcnt);
    cudaFuncSetAttribute(vq_kernel, cudaFuncAttributeMaxDynamicSharedMemorySize, VQ_SMEM_BYTES);
    vq_kernel<<<VQ_NPOS / 256, 256, VQ_SMEM_BYTES>>>(o_ze, cbs, o_zq, gpart, gcnt);
    vq_finalize<<<1, 128>>>(gpart, gcnt, o_loss, o_perp);

    // ---------------- Decoder ----------------
    conv2d(0, o_zq, dec_w1, dec_b1, nullptr, ga, 16, 64, 64, 64, 256, 64, 64, 3, 3, 1, 1, false, false);
    // res block 0
    conv2d(2, ga,   dec_rw1,         dec_rb1,       nullptr, gmid, 16, 256, 64, 64,  32, 64, 64, 3, 3, 1, 1, true, false);
    conv2d(0, gmid, dec_rw2,         dec_rb2,       ga,      gb,   16,  32, 64, 64, 256, 64, 64, 1, 1, 1, 0, true, false);
    // res block 1
    conv2d(2, gb,   dec_rw1 + 73728, dec_rb1 + 32,  nullptr, gmid, 16, 256, 64, 64,  32, 64, 64, 3, 3, 1, 1, true, false);
    conv2d(0, gmid, dec_rw2 + 8192,  dec_rb2 + 256, gb,      ga,   16,  32, 64, 64, 256, 64, 64, 1, 1, 1, 0, true, false);
    // conv_t1 (final res-stack relu folded in) -> relu'd [16,128,128,128]
    convT(ga, t1w, t1b, h1, 16, 256, 64, 64, 128, true, true);
    // conv_t2 -> x_recon
    convt2_kernel<<<4096, 256>>>(h1, t2w, t2b, o_xrec);
}

// round 9
// speedup vs baseline: 1.6033x; 1.0862x over previous
#include <cuda_runtime.h>
#include <math.h>

// ============================================================
// Scratch (device globals -- no allocation allowed)
// ============================================================
__device__ float g_h1 [33554432];  // [16,128,128,128]
__device__ float g_a  [16777216];  // [16,256,64,64]
__device__ float g_b  [16777216];  // [16,256,64,64]
__device__ float g_mid[ 2097152];  // [16,32,64,64]
__device__ float g_wT [2304*256];  // transposed weights [K][Cout]
__device__ float g_part[256 * 4];
__device__ int   g_cnt [4 * 512];

// Output layout (tuple order): x_recon | rq_loss | z_q | z_e | perps
#define OFF_XREC 0
#define OFF_LOSS 3145728
#define OFF_ZQ   3145729
#define OFF_ZE   7340033
#define OFF_PERP 11534337

#define BK 8
#define KMAX 2304

struct ConvParams {
    const float* in; const float* bias; const float* residual; float* out;
    int Cin, IH, IW, Cout, OH, OW;
    int KHW, KW, Kdim;
    int stride, padH, padW;
    int OHfull, OWfull, oyOff, oyStep, oxOff, oxStep;
    int inRelu, outRelu, addRes;
};

// ============================================================
// Weight transpose: w (arbitrary tap strides) -> wT[k][Cout]
// ============================================================
__global__ void wtrans_kernel(const float* __restrict__ w, float* __restrict__ wT,
                              int Cout, int Kdim, int KHW, int KW,
                              int wsCo, int wsCi, int wsKy,
                              int kyOff, int kyStep, int kxOff, int kxStep)
{
    int idx = blockIdx.x * 256 + threadIdx.x;
    if (idx >= Kdim * Cout) return;
    int k = idx / Cout, m = idx - k * Cout;
    int ci = k / KHW, r2 = k - ci * KHW;
    int ky = r2 / KW, kx = r2 - ky * KW;
    wT[idx] = w[m * wsCo + ci * wsCi + (kyOff + ky * kyStep) * wsKy + kxOff + kx * kxStep];
}

// ============================================================
// Implicit-GEMM conv, double-buffered, BN=64, 2 CTAs/SM
// ============================================================
template<int BM, int TM, int TN>
__global__ __launch_bounds__(256, 2) void conv_gemm3(ConvParams p, const float* __restrict__ wT)
{
    constexpr int NG = 64 / TN;          // n groups (threads along N)
    __shared__ float As[2][BK][BM + 4];
    __shared__ float Bs[2][BK][64 + 4];
    __shared__ int sBOff[KMAX];
    __shared__ int sKyx [KMAX];

    const int tid  = threadIdx.x;
    const int Kdim = p.Kdim;

    for (int k = tid; k < Kdim; k += 256) {
        int ci = k / p.KHW, r2 = k - ci * p.KHW;
        int ky = r2 / p.KW, kx = r2 - ky * p.KW;
        sBOff[k] = (ci * p.IH + ky) * p.IW + kx;
        sKyx[k]  = (ky << 16) | kx;
    }

    const int lk   = tid >> 5;           // k-row for loaders
    const int ln2  = (tid & 31) << 1;    // 2 B-cols per thread
    const int OHOW = p.OH * p.OW;
    const int Cout = p.Cout;
    const int mBase = blockIdx.x * BM;

    // B-column precompute (2 cols per thread)
    int inB[2], iy0a[2], ix0a[2];
    {
        int colBase = blockIdx.y * 64 + ln2;
#pragma unroll
        for (int j = 0; j < 2; j++) {
            int col = colBase + j;
            int n2 = col / OHOW; int rr = col - n2 * OHOW;
            int oy = rr / p.OW;  int ox = rr - oy * p.OW;
            int iy0 = oy * p.stride - p.padH;
            int ix0 = ox * p.stride - p.padW;
            iy0a[j] = iy0; ix0a[j] = ix0;
            inB[j]  = (n2 * p.Cin * p.IH + iy0) * p.IW + ix0;
        }
    }

    float acc[TM][TN];
#pragma unroll
    for (int i = 0; i < TM; i++)
#pragma unroll
        for (int j = 0; j < TN; j++) acc[i][j] = 0.f;

    float4 aR;  // A prefetch regs (x,y used for BM=64; x for BM=32)
    float  bR0, bR1;

    auto loadA = [&](int k0) {
        int kg = k0 + lk;
        if constexpr (BM == 128) {
            aR = *(const float4*)(wT + (size_t)kg * Cout + mBase + ((tid & 31) << 2));
        } else if constexpr (BM == 64) {
            const float2 t2 = *(const float2*)(wT + (size_t)kg * Cout + mBase + ((tid & 31) << 1));
            aR.x = t2.x; aR.y = t2.y;
        } else {
            aR.x = wT[(size_t)kg * Cout + mBase + (tid & 31)];
        }
    };
    auto loadB = [&](int k0) {
        int kg = k0 + lk;
        int off = sBOff[kg];
        int kyx = sKyx[kg];
        int ky = kyx >> 16, kx = kyx & 0xffff;
        float v[2];
#pragma unroll
        for (int j = 0; j < 2; j++) {
            int iy = iy0a[j] + ky, ix = ix0a[j] + kx;
            float t = 0.f;
            if ((unsigned)iy < (unsigned)p.IH && (unsigned)ix < (unsigned)p.IW) {
                t = __ldg(p.in + inB[j] + off);
                if (p.inRelu) t = fmaxf(t, 0.f);
            }
            v[j] = t;
        }
        bR0 = v[0]; bR1 = v[1];
    };
    auto store = [&](int buf) {
        if constexpr (BM == 128) {
            *(float4*)&As[buf][lk][(tid & 31) << 2] = aR;
        } else if constexpr (BM == 64) {
            int m2 = (tid & 31) << 1;
            As[buf][lk][m2] = aR.x; As[buf][lk][m2 + 1] = aR.y;
        } else {
            As[buf][lk][tid & 31] = aR.x;
        }
        Bs[buf][lk][ln2] = bR0; Bs[buf][lk][ln2 + 1] = bR1;
    };

    __syncthreads();          // tables ready
    loadA(0); loadB(0); store(0);
    __syncthreads();

    const int nkb = Kdim / BK;
    const int tym = tid / NG;            // m group
    const int txn = tid % NG;            // n group

    for (int kb = 0; kb < nkb; kb++) {
        int cur = kb & 1;
        if (kb + 1 < nkb) { loadA((kb + 1) * BK); loadB((kb + 1) * BK); }
#pragma unroll
        for (int kk = 0; kk < BK; kk++) {
            float a[TM], b[TN];
#pragma unroll
            for (int s = 0; s < TM / 4; s++)
                *(float4*)&a[s * 4] = *(const float4*)&As[cur][kk][tym * TM + s * 4];
            if constexpr (TN == 4) {
                *(float4*)&b[0] = *(const float4*)&Bs[cur][kk][txn * 4];
            } else {
                const float2 t2 = *(const float2*)&Bs[cur][kk][txn * 2];
                b[0] = t2.x; b[1] = t2.y;
            }
#pragma unroll
            for (int i = 0; i < TM; i++)
#pragma unroll
                for (int j = 0; j < TN; j++)
                    acc[i][j] = fmaf(a[i], b[j], acc[i][j]);
        }
        if (kb + 1 < nkb) store(cur ^ 1);
        __syncthreads();
    }

    // Epilogue: bias (+residual) (+relu), strided/offset output for conv_t classes
    int colNC[TN], colRow[TN];
#pragma unroll
    for (int j = 0; j < TN; j++) {
        int col = blockIdx.y * 64 + txn * TN + j;
        int n2 = col / OHOW; int rr = col - n2 * OHOW;
        int oy = rr / p.OW;  int ox = rr - oy * p.OW;
        colNC[j]  = n2 * Cout;
        colRow[j] = (p.oyOff + oy * p.oyStep) * p.OWfull + p.oxOff + ox * p.oxStep;
    }
    const size_t plane = (size_t)p.OHfull * p.OWfull;
#pragma unroll
    for (int i = 0; i < TM; i++) {
        int m = mBase + tym * TM + i;
        float bi = __ldg(p.bias + m);
#pragma unroll
        for (int j = 0; j < TN; j++) {
            float v = acc[i][j] + bi;
            size_t oidx = (size_t)(colNC[j] + m) * plane + colRow[j];
            if (p.addRes) v += __ldg(p.residual + oidx);
            if (p.outRelu) v = fmaxf(v, 0.f);
            p.out[oidx] = v;
        }
    }
}

// ============================================================
// Dedicated conv_t2 (Cout=3): [16,128,128,128] -> [16,3,256,256]
// ============================================================
__global__ __launch_bounds__(256) void convt2_kernel(
    const float* __restrict__ in, const float* __restrict__ w,
    const float* __restrict__ bias, float* __restrict__ out)
{
    __shared__ float sw[3 * 128 * 16];
    const int tid = threadIdx.x;
    for (int i = tid; i < 6144; i += 256) sw[i] = w[i];
    __syncthreads();

    int idx = blockIdx.x * 256 + tid;
    int ox = idx & 255;
    int oy = (idx >> 8) & 255;
    int n  = idx >> 16;
    int py = oy & 1, px = ox & 1;
    int iyb = ((oy + py) >> 1) - 1;
    int ixb = ((ox + px) >> 1) - 1;

    float acc0 = __ldg(bias + 0), acc1 = __ldg(bias + 1), acc2 = __ldg(bias + 2);
    const float* inb = in + (size_t)n * 128 * 128 * 128;

    for (int ci = 0; ci < 128; ci++) {
        const float* ic = inb + ci * 16384;
#pragma unroll
        for (int ty = 0; ty < 2; ty++) {
            int iy = iyb + ty;
            if ((unsigned)iy < 128u) {
#pragma unroll
                for (int tx2 = 0; tx2 < 2; tx2++) {
                    int ix = ixb + tx2;
                    if ((unsigned)ix < 128u) {
                        float v  = __ldg(ic + iy * 128 + ix);
                        int   wi = (py + 2 * ty) * 4 + (px + 2 * tx2);
                        acc0 = fmaf(v, sw[(0 * 128 + ci) * 16 + wi], acc0);
                        acc1 = fmaf(v, sw[(1 * 128 + ci) * 16 + wi], acc1);
                        acc2 = fmaf(v, sw[(2 * 128 + ci) * 16 + wi], acc2);
                    }
                }
            }
        }
    }
    size_t base = (size_t)n * 3 * 65536 + oy * 256 + ox;
    out[base]             = acc0;
    out[base + 65536]     = acc1;
    out[base + 2 * 65536] = acc2;
}

// ============================================================
// Residual VQ (verified R1/R2)
// ============================================================
#define VQ_SMEM_BYTES ((512*64 + 512 + 512 + 32) * 4)

__global__ __launch_bounds__(256) void vq_kernel(
    const float* __restrict__ z_e, const float* __restrict__ codebooks,
    float* __restrict__ z_q, float* __restrict__ partial, int* __restrict__ counts)
{
    extern __shared__ float sh[];
    float* cb    = sh;
    float* cnorm = sh + 512 * 64;
    int*   hist  = (int*)(sh + 512 * 64 + 512);
    float* red   = sh + 512 * 64 + 512 + 512;

    const int tid = threadIdx.x;
    const int p   = blockIdx.x * 256 + tid;
    const int n   = p >> 12;
    const int hw  = p & 4095;
    const float* zp = z_e + (size_t)n * 262144 + hw;

    float r[64];
#pragma unroll
    for (int d = 0; d < 64; d++) r[d] = __ldg(zp + d * 4096);

    for (int level = 0; level < 4; level++) {
        const float4* src = (const float4*)(codebooks + (size_t)level * 32768);
        float4* dst = (float4*)cb;
        for (int i = tid; i < 8192; i += 256) dst[i] = src[i];
        hist[tid] = 0; hist[tid + 256] = 0;
        __syncthreads();
        for (int c = tid; c < 512; c += 256) {
            const float* cc = cb + c * 64;
            float s = 0.f;
#pragma unroll
            for (int d = 0; d < 64; d++) s = fmaf(cc[d], cc[d], s);
            cnorm[c] = s;
        }
        __syncthreads();

        float best = 3.0e38f; int bidx = 0;
        for (int c = 0; c < 512; c++) {
            const float4* cc = (const float4*)(cb + (c << 6));
            float d0 = 0.f, d1 = 0.f, d2 = 0.f, d3 = 0.f;
#pragma unroll
            for (int i = 0; i < 16; i++) {
                float4 v = cc[i];
                d0 = fmaf(v.x, r[4*i+0], d0);
                d1 = fmaf(v.y, r[4*i+1], d1);
                d2 = fmaf(v.z, r[4*i+2], d2);
                d3 = fmaf(v.w, r[4*i+3], d3);
            }
            float score = cnorm[c] - 2.f * ((d0 + d1) + (d2 + d3));
            if (score < best) { best = score; bidx = c; }
        }
        atomicAdd(&hist[bidx], 1);

        const float* q = cb + (bidx << 6);
        float lsum = 0.f;
#pragma unroll
        for (int d = 0; d < 64; d++) {
            float diff = q[d] - r[d];
            lsum = fmaf(diff, diff, lsum);
            r[d] = -diff;
        }
        float v = lsum;
#pragma unroll
        for (int o = 16; o > 0; o >>= 1) v += __shfl_xor_sync(0xffffffffu, v, o);
        if ((tid & 31) == 0) red[tid >> 5] = v;
        __syncthreads();
        if (tid == 0) {
            float t = 0.f;
            for (int i = 0; i < 8; i++) t += red[i];
            partial[blockIdx.x * 4 + level] = t;
        }
        atomicAdd(&counts[level * 512 + tid],       hist[tid]);
        atomicAdd(&counts[level * 512 + tid + 256], hist[tid + 256]);
        __syncthreads();
    }

    float* oq = z_q + (size_t)n * 262144 + hw;
#pragma unroll
    for (int d = 0; d < 64; d++) oq[d * 4096] = __ldg(zp + d * 4096) - r[d];
}

__global__ void vq_zero(float* partial, int* counts)
{
    int i = blockIdx.x * 256 + threadIdx.x;
    if (i < 1024) partial[i] = 0.f;
    if (i < 2048) counts[i]  = 0;
}

__global__ void vq_finalize(const float* __restrict__ partial, const int* __restrict__ counts,
                            float* __restrict__ out_loss, float* __restrict__ out_perp)
{
    __shared__ float losses[4];
    int tid = threadIdx.x;
    if (tid < 4) {
        float e = 0.f;
        for (int b = 0; b < 256; b++) e += partial[b * 4 + tid];
        e /= (65536.f * 64.f);
        losses[tid] = 0.25f * e;
        float s = 0.f;
        for (int c = 0; c < 512; c++) {
            float pr = (float)counts[tid * 512 + c] / 65536.f;
            s += pr * logf(pr + 1e-10f);
        }
        out_perp[tid] = expf(-s);
    }
    __syncthreads();
    if (tid == 0)
        out_loss[0] = 0.25f * (losses[0] + losses[1] + losses[2] + losses[3]);
}

// ============================================================
// Host-side launch helpers
// ============================================================
static float* s_wT = nullptr;

static void launch_conv(int cfg, ConvParams& p, const float* wT, int gx, int gy)
{
    dim3 g(gx, gy);
    if (cfg == 0)      conv_gemm3<128, 8, 4><<<g, 256>>>(p, wT);
    else if (cfg == 1) conv_gemm3< 64, 4, 4><<<g, 256>>>(p, wT);
    else               conv_gemm3< 32, 4, 2><<<g, 256>>>(p, wT);
}

static void conv2d(int cfg, const float* in, const float* w, const float* bias, const float* res,
                   float* out, int N, int Cin, int IH, int IW, int Cout, int OH, int OW,
                   int KH, int KW, int stride, int pad, bool inRelu, bool outRelu)
{
    int Kdim = Cin * KH * KW;
    wtrans_kernel<<<(Kdim * Cout + 255) / 256, 256>>>(
        w, s_wT, Cout, Kdim, KH * KW, KW,
        Cin * KH * KW, KH * KW, KW, 0, 1, 0, 1);

    ConvParams p;
    p.in = in; p.bias = bias; p.residual = res; p.out = out;
    p.Cin = Cin; p.IH = IH; p.IW = IW; p.Cout = Cout; p.OH = OH; p.OW = OW;
    p.KHW = KH * KW; p.KW = KW; p.Kdim = Kdim;
    p.stride = stride; p.padH = pad; p.padW = pad;
    p.OHfull = OH; p.OWfull = OW; p.oyOff = 0; p.oyStep = 1; p.oxOff = 0; p.oxStep = 1;
    p.inRelu = inRelu ? 1 : 0; p.outRelu = outRelu ? 1 : 0; p.addRes = (res != nullptr) ? 1 : 0;

    int BMsel = (cfg == 0) ? 128 : (cfg == 1) ? 64 : 32;
    launch_conv(cfg, p, s_wT, Cout / BMsel, (N * OH * OW) / 64);
}

// ConvTranspose2d(k=4,s=2,p=1) as 4 parity-class stride-1 2x2 convs
static void convT(const float* in, const float* w, const float* bias, float* out,
                  int N, int Cin, int IH, int IW, int Cout, bool inRelu, bool outRelu)
{
    int Kdim = Cin * 4;
    for (int py = 0; py < 2; py++)
        for (int px = 0; px < 2; px++) {
            float* wT = s_wT + (py * 2 + px) * Kdim * Cout;
            wtrans_kernel<<<(Kdim * Cout + 255) / 256, 256>>>(
                w, wT, Cout, Kdim, 4, 2,
                Cin * 16, 16, 4, py, 2, px, 2);

            ConvParams p;
            p.in = in; p.bias = bias; p.residual = nullptr; p.out = out;
            p.Cin = Cin; p.IH = IH; p.IW = IW; p.Cout = Cout; p.OH = IH; p.OW = IW;
            p.KHW = 4; p.KW = 2; p.Kdim = Kdim;
            p.stride = 1; p.padH = 1 - py; p.padW = 1 - px;
            p.OHfull = 2 * IH; p.OWfull = 2 * IW;
            p.oyOff = py; p.oyStep = 2; p.oxOff = px; p.oxStep = 2;
            p.inRelu = inRelu ? 1 : 0; p.outRelu = outRelu ? 1 : 0; p.addRes = 0;
            launch_conv(0, p, wT, Cout / 128, (N * IH * IW) / 64);
        }
}

extern "C" void kernel_launch(void* const* d_in, const int* in_sizes, int n_in,
                              void* d_out, int out_size)
{
    (void)in_sizes; (void)n_in; (void)out_size;

    const float* x       = (const float*)d_in[0];
    const float* enc_w1  = (const float*)d_in[1];
    const float* enc_b1  = (const float*)d_in[2];
    const float* enc_w2  = (const float*)d_in[3];
    const float* enc_b2  = (const float*)d_in[4];
    const float* enc_w3  = (const float*)d_in[5];
    const float* enc_b3  = (const float*)d_in[6];
    const float* enc_rw1 = (const float*)d_in[7];
    const float* enc_rb1 = (const float*)d_in[8];
    const float* enc_rw2 = (const float*)d_in[9];
    const float* enc_rb2 = (const float*)d_in[10];
    const float* enc_wp  = (const float*)d_in[11];
    const float* enc_bp  = (const float*)d_in[12];
    const float* dec_w1  = (const float*)d_in[13];
    const float* dec_b1  = (const float*)d_in[14];
    const float* dec_rw1 = (const float*)d_in[15];
    const float* dec_rb1 = (const float*)d_in[16];
    const float* dec_rw2 = (const float*)d_in[17];
    const float* dec_rb2 = (const float*)d_in[18];
    const float* t1w     = (const float*)d_in[19];
    const float* t1b     = (const float*)d_in[20];
    const float* t2w     = (const float*)d_in[21];
    const float* t2b     = (const float*)d_in[22];
    const float* cbs     = (const float*)d_in[23];

    float *h1, *ga, *gb, *gmid, *gpart; int* gcnt;
    cudaGetSymbolAddress((void**)&h1,    g_h1);
    cudaGetSymbolAddress((void**)&ga,    g_a);
    cudaGetSymbolAddress((void**)&gb,    g_b);
    cudaGetSymbolAddress((void**)&gmid,  g_mid);
    cudaGetSymbolAddress((void**)&s_wT,  g_wT);
    cudaGetSymbolAddress((void**)&gpart, g_part);
    cudaGetSymbolAddress((void**)&gcnt,  g_cnt);

    cudaFuncSetAttribute(vq_kernel, cudaFuncAttributeMaxDynamicSharedMemorySize, VQ_SMEM_BYTES);

    float* out    = (float*)d_out;
    float* o_xrec = out + OFF_XREC;
    float* o_loss = out + OFF_LOSS;
    float* o_zq   = out + OFF_ZQ;
    float* o_ze   = out + OFF_ZE;
    float* o_perp = out + OFF_PERP;

    // ---------------- Encoder ----------------
    conv2d(0, x,  enc_w1, enc_b1, nullptr, h1, 16,   3, 256, 256, 128, 128, 128, 4, 4, 2, 1, false, true);
    conv2d(0, h1, enc_w2, enc_b2, nullptr, ga, 16, 128, 128, 128, 256,  64,  64, 4, 4, 2, 1, false, true);
    conv2d(0, ga, enc_w3, enc_b3, nullptr, gb, 16, 256,  64,  64, 256,  64,  64, 3, 3, 1, 1, false, false);
    // res block 0
    conv2d(2, gb,   enc_rw1,         enc_rb1,       nullptr, gmid, 16, 256, 64, 64,  32, 64, 64, 3, 3, 1, 1, true, false);
    conv2d(0, gmid, enc_rw2,         enc_rb2,       gb,      ga,   16,  32, 64, 64, 256, 64, 64, 1, 1, 1, 0, true, false);
    // res block 1
    conv2d(2, ga,   enc_rw1 + 73728, enc_rb1 + 32,  nullptr, gmid, 16, 256, 64, 64,  32, 64, 64, 3, 3, 1, 1, true, false);
    conv2d(0, gmid, enc_rw2 + 8192,  enc_rb2 + 256, ga,      gb,   16,  32, 64, 64, 256, 64, 64, 1, 1, 1, 0, true, false);
    // projection (final res-stack relu folded into inRelu) -> z_e
    conv2d(1, gb, enc_wp, enc_bp, nullptr, o_ze, 16, 256, 64, 64, 64, 64, 64, 1, 1, 1, 0, true, false);

    // ---------------- Residual VQ ----------------
    vq_zero<<<8, 256>>>(gpart, gcnt);
    vq_kernel<<<256, 256, VQ_SMEM_BYTES>>>(o_ze, cbs, o_zq, gpart, gcnt);
    vq_finalize<<<1, 128>>>(gpart, gcnt, o_loss, o_perp);

    // ---------------- Decoder ----------------
    conv2d(0, o_zq, dec_w1, dec_b1, nullptr, ga, 16, 64, 64, 64, 256, 64, 64, 3, 3, 1, 1, false, false);
    // res block 0
    conv2d(2, ga,   dec_rw1,         dec_rb1,       nullptr, gmid, 16, 256, 64, 64,  32, 64, 64, 3, 3, 1, 1, true, false);
    conv2d(0, gmid, dec_rw2,         dec_rb2,       ga,      gb,   16,  32, 64, 64, 256, 64, 64, 1, 1, 1, 0, true, false);
    // res block 1
    conv2d(2, gb,   dec_rw1 + 73728, dec_rb1 + 32,  nullptr, gmid, 16, 256, 64, 64,  32, 64, 64, 3, 3, 1, 1, true, false);
    conv2d(0, gmid, dec_rw2 + 8192,  dec_rb2 + 256, gb,      ga,   16,  32, 64, 64, 256, 64, 64, 1, 1, 1, 0, true, false);
    // conv_t1 (final res-stack relu folded in) -> relu'd [16,128,128,128]
    convT(ga, t1w, t1b, h1, 16, 256, 64, 64, 128, true, true);
    // conv_t2 -> x_recon
    convt2_kernel<<<4096, 256>>>(h1, t2w, t2b, o_xrec);
}

// round 10
// speedup vs baseline: 1.7499x; 1.0914x over previous
#include <cuda_runtime.h>
#include <math.h>
#include <stdint.h>

typedef unsigned long long u64;

// ============================================================
// Scratch (device globals -- no allocation allowed)
// ============================================================
__device__ float g_h1 [33554432];  // [16,128,128,128]
__device__ float g_a  [16777216];  // [16,256,64,64]
__device__ float g_b  [16777216];  // [16,256,64,64]
__device__ float g_mid[ 2097152];  // [16,32,64,64]
__device__ float g_wT [2304*256];  // transposed weights [K][Cout]
__device__ float g_part[256 * 4];
__device__ int   g_cnt [4 * 512];

// Output layout (tuple order): x_recon | rq_loss | z_q | z_e | perps
#define OFF_XREC 0
#define OFF_LOSS 3145728
#define OFF_ZQ   3145729
#define OFF_ZE   7340033
#define OFF_PERP 11534337

#define BK 8
#define KMAX 2304

// ---- packed fp32x2 helpers (FFMA2 path; sm_100+ base PTX feature) ----
__device__ __forceinline__ u64 pack2(float x){
    u64 r; asm("mov.b64 %0, {%1, %1};" : "=l"(r) : "f"(x)); return r;
}
__device__ __forceinline__ void fma2(u64& acc, u64 a, u64 b){
    asm("fma.rn.f32x2 %0, %1, %2, %0;" : "+l"(acc) : "l"(a), "l"(b));
}
__device__ __forceinline__ float2 unpack2(u64 v){
    float2 f; asm("mov.b64 {%0, %1}, %2;" : "=f"(f.x), "=f"(f.y) : "l"(v)); return f;
}

struct ConvParams {
    const float* in; const float* bias; const float* residual; float* out;
    int Cin, IH, IW, Cout, OH, OW;
    int KHW, KW, Kdim;
    int stride, padH, padW;
    int OHfull, OWfull, oyOff, oyStep, oxOff, oxStep;
    int inRelu, outRelu, addRes;
};

// ============================================================
// Weight transpose: w (arbitrary tap strides) -> wT[k][Cout]
// ============================================================
__global__ void wtrans_kernel(const float* __restrict__ w, float* __restrict__ wT,
                              int Cout, int Kdim, int KHW, int KW,
                              int wsCo, int wsCi, int wsKy,
                              int kyOff, int kyStep, int kxOff, int kxStep)
{
    int idx = blockIdx.x * 256 + threadIdx.x;
    if (idx >= Kdim * Cout) return;
    int k = idx / Cout, m = idx - k * Cout;
    int ci = k / KHW, r2 = k - ci * KHW;
    int ky = r2 / KW, kx = r2 - ky * KW;
    wT[idx] = w[m * wsCo + ci * wsCi + (kyOff + ky * kyStep) * wsKy + kxOff + kx * kxStep];
}

// ============================================================
// Implicit-GEMM conv, double-buffered, BN=128, FFMA2 microkernel
// ============================================================
template<int BM, int TM, int TN>
__global__ __launch_bounds__(256, 2) void conv_gemm4(ConvParams p, const float* __restrict__ wT)
{
    constexpr int NG = 128 / TN;         // n groups
    constexpr int NP = TN / 2;           // packed pairs along N
    __shared__ __align__(16) float As[2][BK][BM + 4];
    __shared__ __align__(16) float Bs[2][BK][128 + 4];
    __shared__ int sBOff[KMAX];
    __shared__ int sKyx [KMAX];

    const int tid  = threadIdx.x;
    const int Kdim = p.Kdim;

    for (int k = tid; k < Kdim; k += 256) {
        int ci = k / p.KHW, r2 = k - ci * p.KHW;
        int ky = r2 / p.KW, kx = r2 - ky * p.KW;
        sBOff[k] = (ci * p.IH + ky) * p.IW + kx;
        sKyx[k]  = (ky << 16) | kx;
    }

    const int lk   = tid >> 5;           // k-row for loaders
    const int ln4  = (tid & 31) << 2;    // 4 B-cols per thread
    const int OHOW = p.OH * p.OW;
    const int Cout = p.Cout;
    const int mBase = blockIdx.x * BM;

    // B-column precompute (4 cols per thread)
    int inB[4], iy0a[4], ix0a[4];
    {
        int colBase = blockIdx.y * 128 + ln4;
#pragma unroll
        for (int j = 0; j < 4; j++) {
            int col = colBase + j;
            int n2 = col / OHOW; int rr = col - n2 * OHOW;
            int oy = rr / p.OW;  int ox = rr - oy * p.OW;
            int iy0 = oy * p.stride - p.padH;
            int ix0 = ox * p.stride - p.padW;
            iy0a[j] = iy0; ix0a[j] = ix0;
            inB[j]  = (n2 * p.Cin * p.IH + iy0) * p.IW + ix0;
        }
    }

    u64 acc[TM][NP];
#pragma unroll
    for (int i = 0; i < TM; i++)
#pragma unroll
        for (int j = 0; j < NP; j++) acc[i][j] = 0ull;

    float4 aR, bR;

    auto loadA = [&](int k0) {
        int kg = k0 + lk;
        if constexpr (BM == 128) {
            aR = *(const float4*)(wT + (size_t)kg * Cout + mBase + ((tid & 31) << 2));
        } else if constexpr (BM == 64) {
            const float2 t2 = *(const float2*)(wT + (size_t)kg * Cout + mBase + ((tid & 31) << 1));
            aR.x = t2.x; aR.y = t2.y;
        } else {
            aR.x = wT[(size_t)kg * Cout + mBase + (tid & 31)];
        }
    };
    auto loadB = [&](int k0) {
        int kg = k0 + lk;
        int off = sBOff[kg];
        int kyx = sKyx[kg];
        int ky = kyx >> 16, kx = kyx & 0xffff;
        float v[4];
#pragma unroll
        for (int j = 0; j < 4; j++) {
            int iy = iy0a[j] + ky, ix = ix0a[j] + kx;
            float t = 0.f;
            if ((unsigned)iy < (unsigned)p.IH && (unsigned)ix < (unsigned)p.IW) {
                t = __ldg(p.in + inB[j] + off);
                if (p.inRelu) t = fmaxf(t, 0.f);
            }
            v[j] = t;
        }
        bR = make_float4(v[0], v[1], v[2], v[3]);
    };
    auto store = [&](int buf) {
        if constexpr (BM == 128) {
            *(float4*)&As[buf][lk][(tid & 31) << 2] = aR;
        } else if constexpr (BM == 64) {
            int m2 = (tid & 31) << 1;
            As[buf][lk][m2] = aR.x; As[buf][lk][m2 + 1] = aR.y;
        } else {
            As[buf][lk][tid & 31] = aR.x;
        }
        *(float4*)&Bs[buf][lk][ln4] = bR;
    };

    __syncthreads();          // tables ready
    loadA(0); loadB(0); store(0);
    __syncthreads();

    const int nkb = Kdim / BK;
    const int tym = tid / NG;            // m group
    const int txn = tid % NG;            // n group

    for (int kb = 0; kb < nkb; kb++) {
        int cur = kb & 1;
        if (kb + 1 < nkb) { loadA((kb + 1) * BK); loadB((kb + 1) * BK); }
#pragma unroll
        for (int kk = 0; kk < BK; kk++) {
            float a[TM];
            u64 pb[NP];
#pragma unroll
            for (int s = 0; s < TM / 4; s++)
                *(float4*)&a[s * 4] = *(const float4*)&As[cur][kk][tym * TM + s * 4];
#pragma unroll
            for (int u = 0; u < NP / 2; u++) {
                ulonglong2 t = *(const ulonglong2*)&Bs[cur][kk][txn * TN + u * 4];
                pb[u * 2] = t.x; pb[u * 2 + 1] = t.y;
            }
#pragma unroll
            for (int i = 0; i < TM; i++) {
                u64 pa = pack2(a[i]);
#pragma unroll
                for (int j = 0; j < NP; j++)
                    fma2(acc[i][j], pa, pb[j]);
            }
        }
        if (kb + 1 < nkb) store(cur ^ 1);
        __syncthreads();
    }

    // Epilogue: bias (+residual) (+relu), strided/offset output
    int colNC[TN], colRow[TN];
#pragma unroll
    for (int j = 0; j < TN; j++) {
        int col = blockIdx.y * 128 + txn * TN + j;
        int n2 = col / OHOW; int rr = col - n2 * OHOW;
        int oy = rr / p.OW;  int ox = rr - oy * p.OW;
        colNC[j]  = n2 * Cout;
        colRow[j] = (p.oyOff + oy * p.oyStep) * p.OWfull + p.oxOff + ox * p.oxStep;
    }
    const size_t plane = (size_t)p.OHfull * p.OWfull;
#pragma unroll
    for (int i = 0; i < TM; i++) {
        int m = mBase + tym * TM + i;
        float bi = __ldg(p.bias + m);
#pragma unroll
        for (int jp = 0; jp < NP; jp++) {
            float2 v2 = unpack2(acc[i][jp]);
            float vv[2] = {v2.x, v2.y};
#pragma unroll
            for (int h = 0; h < 2; h++) {
                int j = jp * 2 + h;
                float v = vv[h] + bi;
                size_t oidx = (size_t)(colNC[j] + m) * plane + colRow[j];
                if (p.addRes) v += __ldg(p.residual + oidx);
                if (p.outRelu) v = fmaxf(v, 0.f);
                p.out[oidx] = v;
            }
        }
    }
}

// ============================================================
// Dedicated conv_t2 (Cout=3): [16,128,128,128] -> [16,3,256,256]
// ============================================================
__global__ __launch_bounds__(256) void convt2_kernel(
    const float* __restrict__ in, const float* __restrict__ w,
    const float* __restrict__ bias, float* __restrict__ out)
{
    __shared__ float sw[3 * 128 * 16];
    const int tid = threadIdx.x;
    for (int i = tid; i < 6144; i += 256) sw[i] = w[i];
    __syncthreads();

    int idx = blockIdx.x * 256 + tid;
    int ox = idx & 255;
    int oy = (idx >> 8) & 255;
    int n  = idx >> 16;
    int py = oy & 1, px = ox & 1;
    int iyb = ((oy + py) >> 1) - 1;
    int ixb = ((ox + px) >> 1) - 1;

    float acc0 = __ldg(bias + 0), acc1 = __ldg(bias + 1), acc2 = __ldg(bias + 2);
    const float* inb = in + (size_t)n * 128 * 128 * 128;

    for (int ci = 0; ci < 128; ci++) {
        const float* ic = inb + ci * 16384;
#pragma unroll
        for (int ty = 0; ty < 2; ty++) {
            int iy = iyb + ty;
            if ((unsigned)iy < 128u) {
#pragma unroll
                for (int tx2 = 0; tx2 < 2; tx2++) {
                    int ix = ixb + tx2;
                    if ((unsigned)ix < 128u) {
                        float v  = __ldg(ic + iy * 128 + ix);
                        int   wi = (py + 2 * ty) * 4 + (px + 2 * tx2);
                        acc0 = fmaf(v, sw[(0 * 128 + ci) * 16 + wi], acc0);
                        acc1 = fmaf(v, sw[(1 * 128 + ci) * 16 + wi], acc1);
                        acc2 = fmaf(v, sw[(2 * 128 + ci) * 16 + wi], acc2);
                    }
                }
            }
        }
    }
    size_t base = (size_t)n * 3 * 65536 + oy * 256 + ox;
    out[base]             = acc0;
    out[base + 65536]     = acc1;
    out[base + 2 * 65536] = acc2;
}

// ============================================================
// Residual VQ (verified R1/R2)
// ============================================================
#define VQ_SMEM_BYTES ((512*64 + 512 + 512 + 32) * 4)

__global__ __launch_bounds__(256) void vq_kernel(
    const float* __restrict__ z_e, const float* __restrict__ codebooks,
    float* __restrict__ z_q, float* __restrict__ partial, int* __restrict__ counts)
{
    extern __shared__ float sh[];
    float* cb    = sh;
    float* cnorm = sh + 512 * 64;
    int*   hist  = (int*)(sh + 512 * 64 + 512);
    float* red   = sh + 512 * 64 + 512 + 512;

    const int tid = threadIdx.x;
    const int p   = blockIdx.x * 256 + tid;
    const int n   = p >> 12;
    const int hw  = p & 4095;
    const float* zp = z_e + (size_t)n * 262144 + hw;

    float r[64];
#pragma unroll
    for (int d = 0; d < 64; d++) r[d] = __ldg(zp + d * 4096);

    for (int level = 0; level < 4; level++) {
        const float4* src = (const float4*)(codebooks + (size_t)level * 32768);
        float4* dst = (float4*)cb;
        for (int i = tid; i < 8192; i += 256) dst[i] = src[i];
        hist[tid] = 0; hist[tid + 256] = 0;
        __syncthreads();
        for (int c = tid; c < 512; c += 256) {
            const float* cc = cb + c * 64;
            float s = 0.f;
#pragma unroll
            for (int d = 0; d < 64; d++) s = fmaf(cc[d], cc[d], s);
            cnorm[c] = s;
        }
        __syncthreads();

        float best = 3.0e38f; int bidx = 0;
        for (int c = 0; c < 512; c++) {
            const float4* cc = (const float4*)(cb + (c << 6));
            float d0 = 0.f, d1 = 0.f, d2 = 0.f, d3 = 0.f;
#pragma unroll
            for (int i = 0; i < 16; i++) {
                float4 v = cc[i];
                d0 = fmaf(v.x, r[4*i+0], d0);
                d1 = fmaf(v.y, r[4*i+1], d1);
                d2 = fmaf(v.z, r[4*i+2], d2);
                d3 = fmaf(v.w, r[4*i+3], d3);
            }
            float score = cnorm[c] - 2.f * ((d0 + d1) + (d2 + d3));
            if (score < best) { best = score; bidx = c; }
        }
        atomicAdd(&hist[bidx], 1);

        const float* q = cb + (bidx << 6);
        float lsum = 0.f;
#pragma unroll
        for (int d = 0; d < 64; d++) {
            float diff = q[d] - r[d];
            lsum = fmaf(diff, diff, lsum);
            r[d] = -diff;
        }
        float v = lsum;
#pragma unroll
        for (int o = 16; o > 0; o >>= 1) v += __shfl_xor_sync(0xffffffffu, v, o);
        if ((tid & 31) == 0) red[tid >> 5] = v;
        __syncthreads();
        if (tid == 0) {
            float t = 0.f;
            for (int i = 0; i < 8; i++) t += red[i];
            partial[blockIdx.x * 4 + level] = t;
        }
        atomicAdd(&counts[level * 512 + tid],       hist[tid]);
        atomicAdd(&counts[level * 512 + tid + 256], hist[tid + 256]);
        __syncthreads();
    }

    float* oq = z_q + (size_t)n * 262144 + hw;
#pragma unroll
    for (int d = 0; d < 64; d++) oq[d * 4096] = __ldg(zp + d * 4096) - r[d];
}

__global__ void vq_zero(float* partial, int* counts)
{
    int i = blockIdx.x * 256 + threadIdx.x;
    if (i < 1024) partial[i] = 0.f;
    if (i < 2048) counts[i]  = 0;
}

__global__ void vq_finalize(const float* __restrict__ partial, const int* __restrict__ counts,
                            float* __restrict__ out_loss, float* __restrict__ out_perp)
{
    __shared__ float losses[4];
    int tid = threadIdx.x;
    if (tid < 4) {
        float e = 0.f;
        for (int b = 0; b < 256; b++) e += partial[b * 4 + tid];
        e /= (65536.f * 64.f);
        losses[tid] = 0.25f * e;
        float s = 0.f;
        for (int c = 0; c < 512; c++) {
            float pr = (float)counts[tid * 512 + c] / 65536.f;
            s += pr * logf(pr + 1e-10f);
        }
        out_perp[tid] = expf(-s);
    }
    __syncthreads();
    if (tid == 0)
        out_loss[0] = 0.25f * (losses[0] + losses[1] + losses[2] + losses[3]);
}

// ============================================================
// Host-side launch helpers
// ============================================================
static float* s_wT = nullptr;

static void launch_conv(int cfg, ConvParams& p, const float* wT, int gx, int gy)
{
    dim3 g(gx, gy);
    if (cfg == 0)      conv_gemm4<128, 8, 8><<<g, 256>>>(p, wT);
    else if (cfg == 1) conv_gemm4< 64, 8, 4><<<g, 256>>>(p, wT);
    else               conv_gemm4< 32, 4, 4><<<g, 256>>>(p, wT);
}

static void conv2d(int cfg, const float* in, const float* w, const float* bias, const float* res,
                   float* out, int N, int Cin, int IH, int IW, int Cout, int OH, int OW,
                   int KH, int KW, int stride, int pad, bool inRelu, bool outRelu)
{
    int Kdim = Cin * KH * KW;
    wtrans_kernel<<<(Kdim * Cout + 255) / 256, 256>>>(
        w, s_wT, Cout, Kdim, KH * KW, KW,
        Cin * KH * KW, KH * KW, KW, 0, 1, 0, 1);

    ConvParams p;
    p.in = in; p.bias = bias; p.residual = res; p.out = out;
    p.Cin = Cin; p.IH = IH; p.IW = IW; p.Cout = Cout; p.OH = OH; p.OW = OW;
    p.KHW = KH * KW; p.KW = KW; p.Kdim = Kdim;
    p.stride = stride; p.padH = pad; p.padW = pad;
    p.OHfull = OH; p.OWfull = OW; p.oyOff = 0; p.oyStep = 1; p.oxOff = 0; p.oxStep = 1;
    p.inRelu = inRelu ? 1 : 0; p.outRelu = outRelu ? 1 : 0; p.addRes = (res != nullptr) ? 1 : 0;

    int BMsel = (cfg == 0) ? 128 : (cfg == 1) ? 64 : 32;
    launch_conv(cfg, p, s_wT, Cout / BMsel, (N * OH * OW) / 128);
}

// ConvTranspose2d(k=4,s=2,p=1) as 4 parity-class stride-1 2x2 convs
static void convT(const float* in, const float* w, const float* bias, float* out,
                  int N, int Cin, int IH, int IW, int Cout, bool inRelu, bool outRelu)
{
    int Kdim = Cin * 4;
    for (int py = 0; py < 2; py++)
        for (int px = 0; px < 2; px++) {
            float* wT = s_wT + (py * 2 + px) * Kdim * Cout;
            wtrans_kernel<<<(Kdim * Cout + 255) / 256, 256>>>(
                w, wT, Cout, Kdim, 4, 2,
                Cin * 16, 16, 4, py, 2, px, 2);

            ConvParams p;
            p.in = in; p.bias = bias; p.residual = nullptr; p.out = out;
            p.Cin = Cin; p.IH = IH; p.IW = IW; p.Cout = Cout; p.OH = IH; p.OW = IW;
            p.KHW = 4; p.KW = 2; p.Kdim = Kdim;
            p.stride = 1; p.padH = 1 - py; p.padW = 1 - px;
            p.OHfull = 2 * IH; p.OWfull = 2 * IW;
            p.oyOff = py; p.oyStep = 2; p.oxOff = px; p.oxStep = 2;
            p.inRelu = inRelu ? 1 : 0; p.outRelu = outRelu ? 1 : 0; p.addRes = 0;
            launch_conv(0, p, wT, Cout / 128, (N * IH * IW) / 128);
        }
}

extern "C" void kernel_launch(void* const* d_in, const int* in_sizes, int n_in,
                              void* d_out, int out_size)
{
    (void)in_sizes; (void)n_in; (void)out_size;

    const float* x       = (const float*)d_in[0];
    const float* enc_w1  = (const float*)d_in[1];
    const float* enc_b1  = (const float*)d_in[2];
    const float* enc_w2  = (const float*)d_in[3];
    const float* enc_b2  = (const float*)d_in[4];
    const float* enc_w3  = (const float*)d_in[5];
    const float* enc_b3  = (const float*)d_in[6];
    const float* enc_rw1 = (const float*)d_in[7];
    const float* enc_rb1 = (const float*)d_in[8];
    const float* enc_rw2 = (const float*)d_in[9];
    const float* enc_rb2 = (const float*)d_in[10];
    const float* enc_wp  = (const float*)d_in[11];
    const float* enc_bp  = (const float*)d_in[12];
    const float* dec_w1  = (const float*)d_in[13];
    const float* dec_b1  = (const float*)d_in[14];
    const float* dec_rw1 = (const float*)d_in[15];
    const float* dec_rb1 = (const float*)d_in[16];
    const float* dec_rw2 = (const float*)d_in[17];
    const float* dec_rb2 = (const float*)d_in[18];
    const float* t1w     = (const float*)d_in[19];
    const float* t1b     = (const float*)d_in[20];
    const float* t2w     = (const float*)d_in[21];
    const float* t2b     = (const float*)d_in[22];
    const float* cbs     = (const float*)d_in[23];

    float *h1, *ga, *gb, *gmid, *gpart; int* gcnt;
    cudaGetSymbolAddress((void**)&h1,    g_h1);
    cudaGetSymbolAddress((void**)&ga,    g_a);
    cudaGetSymbolAddress((void**)&gb,    g_b);
    cudaGetSymbolAddress((void**)&gmid,  g_mid);
    cudaGetSymbolAddress((void**)&s_wT,  g_wT);
    cudaGetSymbolAddress((void**)&gpart, g_part);
    cudaGetSymbolAddress((void**)&gcnt,  g_cnt);

    cudaFuncSetAttribute(vq_kernel, cudaFuncAttributeMaxDynamicSharedMemorySize, VQ_SMEM_BYTES);

    float* out    = (float*)d_out;
    float* o_xrec = out + OFF_XREC;
    float* o_loss = out + OFF_LOSS;
    float* o_zq   = out + OFF_ZQ;
    float* o_ze   = out + OFF_ZE;
    float* o_perp = out + OFF_PERP;

    // ---------------- Encoder ----------------
    conv2d(0, x,  enc_w1, enc_b1, nullptr, h1, 16,   3, 256, 256, 128, 128, 128, 4, 4, 2, 1, false, true);
    conv2d(0, h1, enc_w2, enc_b2, nullptr, ga, 16, 128, 128, 128, 256,  64,  64, 4, 4, 2, 1, false, true);
    conv2d(0, ga, enc_w3, enc_b3, nullptr, gb, 16, 256,  64,  64, 256,  64,  64, 3, 3, 1, 1, false, false);
    // res block 0
    conv2d(2, gb,   enc_rw1,         enc_rb1,       nullptr, gmid, 16, 256, 64, 64,  32, 64, 64, 3, 3, 1, 1, true, false);
    conv2d(0, gmid, enc_rw2,         enc_rb2,       gb,      ga,   16,  32, 64, 64, 256, 64, 64, 1, 1, 1, 0, true, false);
    // res block 1
    conv2d(2, ga,   enc_rw1 + 73728, enc_rb1 + 32,  nullptr, gmid, 16, 256, 64, 64,  32, 64, 64, 3, 3, 1, 1, true, false);
    conv2d(0, gmid, enc_rw2 + 8192,  enc_rb2 + 256, ga,      gb,   16,  32, 64, 64, 256, 64, 64, 1, 1, 1, 0, true, false);
    // projection (final res-stack relu folded into inRelu) -> z_e
    conv2d(1, gb, enc_wp, enc_bp, nullptr, o_ze, 16, 256, 64, 64, 64, 64, 64, 1, 1, 1, 0, true, false);

    // ---------------- Residual VQ ----------------
    vq_zero<<<8, 256>>>(gpart, gcnt);
    vq_kernel<<<256, 256, VQ_SMEM_BYTES>>>(o_ze, cbs, o_zq, gpart, gcnt);
    vq_finalize<<<1, 128>>>(gpart, gcnt, o_loss, o_perp);

    // ---------------- Decoder ----------------
    conv2d(0, o_zq, dec_w1, dec_b1, nullptr, ga, 16, 64, 64, 64, 256, 64, 64, 3, 3, 1, 1, false, false);
    // res block 0
    conv2d(2, ga,   dec_rw1,         dec_rb1,       nullptr, gmid, 16, 256, 64, 64,  32, 64, 64, 3, 3, 1, 1, true, false);
    conv2d(0, gmid, dec_rw2,         dec_rb2,       ga,      gb,   16,  32, 64, 64, 256, 64, 64, 1, 1, 1, 0, true, false);
    // res block 1
    conv2d(2, gb,   dec_rw1 + 73728, dec_rb1 + 32,  nullptr, gmid, 16, 256, 64, 64,  32, 64, 64, 3, 3, 1, 1, true, false);
    conv2d(0, gmid, dec_rw2 + 8192,  dec_rb2 + 256, gb,      ga,   16,  32, 64, 64, 256, 64, 64, 1, 1, 1, 0, true, false);
    // conv_t1 (final res-stack relu folded in) -> relu'd [16,128,128,128]
    convT(ga, t1w, t1b, h1, 16, 256, 64, 64, 128, true, true);
    // conv_t2 -> x_recon
    convt2_kernel<<<4096, 256>>>(h1, t2w, t2b, o_xrec);
}